// round 13
// baseline (speedup 1.0000x reference)
#include <cuda_runtime.h>
#include <cuda_fp16.h>
#include <cstdint>

// ---------------------------------------------------------------------------
// PNN_43095701848191 — build r13: R9 GEMM config (best measured) + fused
// tails via last-CTA tickets (7 launches -> 4).
//
//  prep:     row L2 norms; per-row symmetric int8 quantization
//            (scale = maxabs/127); inverse norms; reset tickets/accums.
//  imma:     CTA 128x128 @ 256 thr (warp tile 32x64), 2 CTAs/SM, K-chunks of
//            128 s8 (SW128), 3-stage cp.async, mma.sync.m16n8k32.s8.
//            dot = (float)i32 * sa * sb is EXACT (|i32| < 2^24).
//            Gauss + class sums; LAST CTA (ticket) runs finalize inline:
//            probs + argmax + write + tier-1 flag (|p1-p0| < 4e-4).
//  fixup16:  gathered fp16 HMMA GEMM over tier-1 rows (f32->f16 on the fly);
//            LAST block rewrites tier-1 rows + flags tier-2 (|gap| < 1e-5).
//  fixup32:  exact fp32 recompute of tier-2 rows; LAST block rewrites them.
// ---------------------------------------------------------------------------

#define TRAIN_N 8192
#define TEST_P  4096
#define KDIM    1024

#define MT 128
#define NT 128
#define NCHUNK 8              // 8 chunks x 128 s8
#define STAGES 3
#define THREADS 256
#define TOTAL_CTAS ((TRAIN_N / NT) * (TEST_P / MT))   // 2048

#define TAU1 4e-4f
#define TAU2 1e-5f
#define NSLICE 32

__device__ __align__(16) uint32_t g_Aq[TEST_P * KDIM / 4];
__device__ __align__(16) uint32_t g_Bq[TRAIN_N * KDIM / 4];
__device__ float g_sa[TEST_P];
__device__ float g_sb[TRAIN_N];
__device__ float g_invte[TEST_P];
__device__ float g_invtr[TRAIN_N];
__device__ float g_tot[TEST_P];
__device__ float g_s1[TEST_P];
__device__ int   g_flagged[TEST_P];
__device__ int   g_flaglist[TEST_P];
__device__ int   g_flagcount;
__device__ float g_ftot[TEST_P];
__device__ float g_fs1[TEST_P];
__device__ int   g_flagged2[TEST_P];
__device__ int   g_f2list[TEST_P];
__device__ int   g_f2count;
__device__ float g_f2tot[TEST_P];
__device__ float g_f2s1[TEST_P];
__device__ int   g_ticket1, g_ticket2, g_ticket3;

__device__ __forceinline__ uint32_t smem_u32(const void* p) {
    uint32_t a;
    asm("{ .reg .u64 t; cvta.to.shared.u64 t, %1; cvt.u32.u64 %0, t; }"
        : "=r"(a) : "l"(p));
    return a;
}

#define SW128(o) ((o) ^ (((o) >> 3) & 0x70))

#define LDSM4(r0, r1, r2, r3, a) \
    asm volatile("ldmatrix.sync.aligned.m8n8.x4.shared.b16 {%0,%1,%2,%3}, [%4];" \
                 : "=r"(r0), "=r"(r1), "=r"(r2), "=r"(r3) : "r"(a))

#define IMMA16832(d, a, b0, b1) \
    asm volatile("mma.sync.aligned.m16n8k32.row.col.s32.s8.s8.s32 " \
                 "{%0,%1,%2,%3}, {%4,%5,%6,%7}, {%8,%9}, {%0,%1,%2,%3};" \
                 : "+r"((d)[0]), "+r"((d)[1]), "+r"((d)[2]), "+r"((d)[3]) \
                 : "r"((a)[0]), "r"((a)[1]), "r"((a)[2]), "r"((a)[3]), \
                   "r"(b0), "r"(b1))

#define HMMA16816(d, a, b0, b1) \
    asm volatile("mma.sync.aligned.m16n8k16.row.col.f32.f16.f16.f32 " \
                 "{%0,%1,%2,%3}, {%4,%5,%6,%7}, {%8,%9}, {%0,%1,%2,%3};" \
                 : "+f"((d)[0]), "+f"((d)[1]), "+f"((d)[2]), "+f"((d)[3]) \
                 : "r"((a)[0]), "r"((a)[1]), "r"((a)[2]), "r"((a)[3]), \
                   "r"(b0), "r"(b1))

#define EX2(out, in) asm("ex2.approx.f32 %0, %1;" : "=f"(out) : "f"(in))
#define GAUSS_C (-2.885390082f)   /* -2 * log2(e) */

__device__ __forceinline__ float gaussf(float dot) {
    float d2 = fmaxf(2.0f - 2.0f * dot, 0.0f);
    float d;
    asm("sqrt.approx.f32 %0, %1;" : "=f"(d) : "f"(d2));
    float g; EX2(g, GAUSS_C * d);
    return g;
}

__device__ __forceinline__ void write_row(float* out, int out_size, int i,
                                          float p0, float p1) {
    float res = (p1 > p0) ? 1.0f : 0.0f;
    if (out_size >= TEST_P * 3) {
        out[i] = res;
        out[TEST_P + 2 * i]     = p0;
        out[TEST_P + 2 * i + 1] = p1;
    } else if (out_size == TEST_P * 2) {
        out[2 * i] = p0;
        out[2 * i + 1] = p1;
    } else {
        out[i] = res;
    }
}

// ---------------------------------------------------------------------------
// Kernel 1: norms, int8 quantization, scales, reset accumulators + tickets.
// ---------------------------------------------------------------------------
__global__ void prep_kernel(const float* __restrict__ train,
                            const float* __restrict__ test) {
    int b = blockIdx.x, t = threadIdx.x;     // 256 threads, 1024 floats/row
    bool isTrain = b < TRAIN_N;
    const float* row = isTrain ? train + (size_t)b * KDIM
                               : test + (size_t)(b - TRAIN_N) * KDIM;
    float4 v = ((const float4*)row)[t];
    float s = v.x * v.x + v.y * v.y + v.z * v.z + v.w * v.w;
    float m = fmaxf(fmaxf(fabsf(v.x), fabsf(v.y)), fmaxf(fabsf(v.z), fabsf(v.w)));
    #pragma unroll
    for (int o = 16; o; o >>= 1) {
        s += __shfl_xor_sync(0xffffffffu, s, o);
        m = fmaxf(m, __shfl_xor_sync(0xffffffffu, m, o));
    }
    __shared__ float ws[8], wm[8];
    __shared__ float s_inv, s_maxn;
    if ((t & 31) == 0) { ws[t >> 5] = s; wm[t >> 5] = m; }
    __syncthreads();
    if (t < 8) {
        float x = ws[t], y = wm[t];
        #pragma unroll
        for (int o = 4; o; o >>= 1) {
            x += __shfl_xor_sync(0xffu, x, o);
            y = fmaxf(y, __shfl_xor_sync(0xffu, y, o));
        }
        if (t == 0) {
            float inv = rsqrtf(x);
            s_inv = inv;
            s_maxn = y * inv;
        }
    }
    __syncthreads();
    float inv = s_inv;
    float qs = 127.0f / s_maxn;

    int q0 = __float2int_rn(v.x * inv * qs), q1 = __float2int_rn(v.y * inv * qs);
    int q2 = __float2int_rn(v.z * inv * qs), q3 = __float2int_rn(v.w * inv * qs);
    uint32_t qw = (uint32_t)(q0 & 255) | ((uint32_t)(q1 & 255) << 8) |
                  ((uint32_t)(q2 & 255) << 16) | ((uint32_t)(q3 & 255) << 24);

    if (isTrain) g_Bq[(size_t)b * 256 + t] = qw;
    else         g_Aq[(size_t)(b - TRAIN_N) * 256 + t] = qw;

    if (t == 0) {
        if (isTrain) {
            g_invtr[b] = inv;
            g_sb[b] = s_maxn * (1.0f / 127.0f);
        } else {
            int bi = b - TRAIN_N;
            g_invte[bi] = inv;
            g_sa[bi] = s_maxn * (1.0f / 127.0f);
            g_tot[bi] = 0.0f;  g_s1[bi] = 0.0f;
            g_ftot[bi] = 0.0f; g_fs1[bi] = 0.0f;
            g_f2tot[bi] = 0.0f; g_f2s1[bi] = 0.0f;
        }
        if (b == 0) {
            g_flagcount = 0; g_f2count = 0;
            g_ticket1 = 0; g_ticket2 = 0; g_ticket3 = 0;
        }
    }
}

// ---------------------------------------------------------------------------
// Kernel 2: int8 IMMA GEMM (R9 config) + fused finalize in the last CTA.
// smem: [0,512) labels; [512,1024) col scales; [1024,1536) row scales;
//       tiles at 2048, 3 x 32 KB.
// ---------------------------------------------------------------------------
#define SLAB_OFF  0
#define SSB_OFF   512
#define SSA_OFF   1024
#define TILES_OFF 2048
#define STAGE_BYTES (MT * 128 + NT * 128)   // 32768
#define B_OFF       (MT * 128)              // 16384
#define SMEM_TOTAL  (TILES_OFF + STAGES * STAGE_BYTES)  // 100352

__device__ __forceinline__ void load_chunk(int tid, uint32_t sb, int stage,
                                           const char* gA, const char* gB,
                                           int chunk) {
    uint32_t base = sb + TILES_OFF + (uint32_t)stage * STAGE_BYTES;
    const char* srcA = gA + (size_t)chunk * 128;
    const char* srcB = gB + (size_t)chunk * 128;
    #pragma unroll
    for (int i = 0; i < 8; i++) {
        int u = tid + THREADS * i;
        const char* src;
        uint32_t dst;
        if (u < 1024) {                 // A tile: 128 rows x 128 B
            int r = u >> 3, c = u & 7;
            src = srcA + (size_t)r * KDIM + c * 16;
            dst = base + SW128((uint32_t)(r * 128 + c * 16));
        } else {                        // B tile: 128 rows x 128 B
            int vv = u - 1024;
            int r = vv >> 3, c = vv & 7;
            src = srcB + (size_t)r * KDIM + c * 16;
            dst = base + B_OFF + SW128((uint32_t)(r * 128 + c * 16));
        }
        asm volatile("cp.async.cg.shared.global [%0], [%1], 16;"
                     :: "r"(dst), "l"(src));
    }
    asm volatile("cp.async.commit_group;" ::: "memory");
}

__global__ __launch_bounds__(THREADS, 2)
void pnn_imma(const int* __restrict__ label, float* __restrict__ out,
              int out_size) {
    extern __shared__ __align__(1024) char smem[];
    uint32_t sb = smem_u32(smem);
    const int tid = threadIdx.x;
    const int wid = tid >> 5, lid = tid & 31;
    const int rowBase = blockIdx.y * MT;      // test rows
    const int colBase = blockIdx.x * NT;      // train rows

    float* slab = (float*)(smem + SLAB_OFF);
    float* ssb  = (float*)(smem + SSB_OFF);
    float* ssa  = (float*)(smem + SSA_OFF);
    if (tid < NT)          slab[tid] = (float)label[colBase + tid];
    else if (tid < 2 * NT) ssb[tid - NT] = g_sb[colBase + tid - NT];
    if (tid < MT)          ssa[tid] = g_sa[rowBase + tid];

    const char* gA = (const char*)g_Aq + (size_t)rowBase * KDIM;
    const char* gB = (const char*)g_Bq + (size_t)colBase * KDIM;

    // warp layout: 4 (m) x 2 (n); warp tile 32 x 64
    const int wm = (wid >> 1) * 32;
    const int wn = (wid & 1) * 64;

    const int aRow = wm + (lid & 15);
    const uint32_t aXor = (uint32_t)((aRow & 7) << 4);
    const uint32_t aHi  = (uint32_t)(((lid >> 4) & 1) << 4);
    const uint32_t aRowOff = (uint32_t)(aRow * 128);
    const int bRow = wn + (lid & 7) + (((lid >> 4) & 1) << 3);
    const uint32_t bXor = (uint32_t)((bRow & 7) << 4);
    const uint32_t bHi  = (uint32_t)(((lid >> 3) & 1) << 4);
    const uint32_t bRowOff = (uint32_t)(bRow * 128);

    int acc[2][8][4];
    #pragma unroll
    for (int mi = 0; mi < 2; mi++)
        #pragma unroll
        for (int n = 0; n < 8; n++)
            #pragma unroll
            for (int c = 0; c < 4; c++) acc[mi][n][c] = 0;

    load_chunk(tid, sb, 0, gA, gB, 0);
    load_chunk(tid, sb, 1, gA, gB, 1);

    #pragma unroll 1
    for (int t = 0; t < NCHUNK; t++) {
        if (t + 1 < NCHUNK) {
            asm volatile("cp.async.wait_group 1;" ::: "memory");
        } else {
            asm volatile("cp.async.wait_group 0;" ::: "memory");
        }
        __syncthreads();
        if (t + 2 < NCHUNK)
            load_chunk(tid, sb, (t + 2) % STAGES, gA, gB, t + 2);

        const uint32_t base = sb + TILES_OFF + (uint32_t)(t % STAGES) * STAGE_BYTES;
        #pragma unroll
        for (int ks = 0; ks < 4; ks++) {
            uint32_t aoff = ((uint32_t)(ks * 32) + aHi) ^ aXor;
            uint32_t boff = ((uint32_t)(ks * 32) + bHi) ^ bXor;
            uint32_t fa[2][4], fb[4][4];
            #pragma unroll
            for (int mi = 0; mi < 2; mi++)
                LDSM4(fa[mi][0], fa[mi][1], fa[mi][2], fa[mi][3],
                      base + aRowOff + mi * 2048 + aoff);
            #pragma unroll
            for (int nj = 0; nj < 4; nj++)
                LDSM4(fb[nj][0], fb[nj][1], fb[nj][2], fb[nj][3],
                      base + B_OFF + bRowOff + nj * 2048 + boff);
            #pragma unroll
            for (int mi = 0; mi < 2; mi++)
                #pragma unroll
                for (int nj = 0; nj < 4; nj++) {
                    IMMA16832(acc[mi][2 * nj],     fa[mi], fb[nj][0], fb[nj][1]);
                    IMMA16832(acc[mi][2 * nj + 1], fa[mi], fb[nj][2], fb[nj][3]);
                }
        }
    }

    // ---- epilogue: i32 -> scaled fp32 dot (exact) -> Gauss -> class sums ----
    #pragma unroll
    for (int mi = 0; mi < 2; mi++) {
        const int r0 = wm + mi * 16 + (lid >> 2);
        const float sa0 = ssa[r0];
        const float sa1 = ssa[r0 + 8];
        float tA = 0.0f, sA = 0.0f, tB = 0.0f, sB = 0.0f;
        #pragma unroll
        for (int n8 = 0; n8 < 8; n8++) {
            #pragma unroll
            for (int j = 0; j < 2; j++) {
                const int col = wn + n8 * 8 + 2 * (lid & 3) + j;
                const float lab = slab[col];
                const float sbv = ssb[col];
                {
                    float g = gaussf((float)acc[mi][n8][j] * (sa0 * sbv));
                    tA += g; sA += g * lab;
                }
                {
                    float g = gaussf((float)acc[mi][n8][2 + j] * (sa1 * sbv));
                    tB += g; sB += g * lab;
                }
            }
        }
        #pragma unroll
        for (int o = 1; o < 4; o <<= 1) {
            tA += __shfl_xor_sync(0xffffffffu, tA, o);
            sA += __shfl_xor_sync(0xffffffffu, sA, o);
            tB += __shfl_xor_sync(0xffffffffu, tB, o);
            sB += __shfl_xor_sync(0xffffffffu, sB, o);
        }
        if ((lid & 3) == 0) {
            int rowA = rowBase + r0;
            atomicAdd(&g_tot[rowA], tA);
            atomicAdd(&g_s1[rowA], sA);
            atomicAdd(&g_tot[rowA + 8], tB);
            atomicAdd(&g_s1[rowA + 8], sB);
        }
    }

    // ---- fused finalize: last CTA (ticket) computes probs/argmax/flags ----
    __threadfence();
    __syncthreads();
    __shared__ int s_last;
    if (tid == 0) {
        int tk = atomicAdd(&g_ticket1, 1);
        s_last = (tk == TOTAL_CTAS - 1) ? 1 : 0;
    }
    __syncthreads();
    if (s_last) {
        __threadfence();   // acquire: order the ldcg reads after ticket
        for (int i = tid; i < TEST_P; i += THREADS) {
            float tot = __ldcg(&g_tot[i]);
            float s1v = __ldcg(&g_s1[i]);
            float p0 = (tot - s1v) / tot, p1 = s1v / tot;
            write_row(out, out_size, i, p0, p1);
            int fl = (fabsf(p1 - p0) < TAU1) ? 1 : 0;
            g_flagged[i] = fl;
            if (fl) {
                int idx = atomicAdd(&g_flagcount, 1);
                g_flaglist[idx] = i;
            }
        }
    }
}

// ---------------------------------------------------------------------------
// Kernel 3: gathered fp16 HMMA GEMM over tier-1 rows (f32->f16 on the fly);
// last block rewrites tier-1 rows and flags tier-2.
// ---------------------------------------------------------------------------
__global__ __launch_bounds__(256)
void fixup16_kernel(const float* __restrict__ train,
                    const float* __restrict__ test,
                    const int* __restrict__ label,
                    float* __restrict__ out, int out_size) {
    __shared__ int sgrow[128];
    __shared__ float sinvA[128];
    __shared__ float sinvB[64];
    __shared__ float slab2[64];
    __shared__ __align__(1024) char tA[16384];   // 128 rows x 128 B (f16)
    __shared__ __align__(1024) char tB[8192];    // 64 rows x 128 B (f16)

    const int F = g_flagcount;
    const int numM = (F + 127) / 128;            // 0 when F == 0
    const int total = numM * 128;
    const int tid = threadIdx.x;
    const int wid = tid >> 5, lid = tid & 31;
    const uint32_t tAb = smem_u32(tA), tBb = smem_u32(tB);

    const int wm = (wid >> 1) * 32;
    const int wn = (wid & 1) * 32;
    const int aRow = wm + (lid & 15);
    const uint32_t aXor = (uint32_t)((aRow & 7) << 4);
    const uint32_t aHi  = (uint32_t)(((lid >> 4) & 1) << 4);
    const uint32_t aRowOff = (uint32_t)(aRow * 128);
    const int bRow = wn + (lid & 7) + (((lid >> 4) & 1) << 3);
    const uint32_t bXor = (uint32_t)((bRow & 7) << 4);
    const uint32_t bHi  = (uint32_t)(((lid >> 3) & 1) << 4);
    const uint32_t bRowOff = (uint32_t)(bRow * 128);

    for (int u = blockIdx.x; u < total; u += gridDim.x) {
        const int mtile = u >> 7;
        const int ntile = u & 127;
        const int colBase = ntile * 64;
        __syncthreads();
        if (tid < 128) {
            int gi = mtile * 128 + tid;
            int row = (gi < F) ? g_flaglist[gi] : 0;
            sgrow[tid] = row;
            sinvA[tid] = g_invte[row];
        } else if (tid < 192) {
            slab2[tid - 128] = (float)label[colBase + tid - 128];
            sinvB[tid - 128] = g_invtr[colBase + tid - 128];
        }
        __syncthreads();

        float acc[2][4][4];
        #pragma unroll
        for (int mi = 0; mi < 2; mi++)
            #pragma unroll
            for (int n = 0; n < 4; n++)
                #pragma unroll
                for (int cc = 0; cc < 4; cc++) acc[mi][n][cc] = 0.0f;

        #pragma unroll 1
        for (int chunk = 0; chunk < 16; chunk++) {
            __syncthreads();
            #pragma unroll
            for (int i = 0; i < 6; i++) {
                int u2 = tid + 256 * i;
                int r, cc;
                const float* src;
                float inv;
                uint32_t dst;
                if (u2 < 1024) {
                    r = u2 >> 3; cc = u2 & 7;
                    src = test + (size_t)sgrow[r] * KDIM + chunk * 64 + cc * 8;
                    inv = sinvA[r];
                    dst = tAb + SW128((uint32_t)(r * 128 + cc * 16));
                } else {
                    int vv = u2 - 1024;
                    r = vv >> 3; cc = vv & 7;
                    src = train + (size_t)(colBase + r) * KDIM + chunk * 64 + cc * 8;
                    inv = sinvB[r];
                    dst = tBb + SW128((uint32_t)(r * 128 + cc * 16));
                }
                float4 v0 = ((const float4*)src)[0];
                float4 v1 = ((const float4*)src)[1];
                union { __half h[8]; uint4 q; } H;
                H.h[0] = __float2half_rn(v0.x * inv);
                H.h[1] = __float2half_rn(v0.y * inv);
                H.h[2] = __float2half_rn(v0.z * inv);
                H.h[3] = __float2half_rn(v0.w * inv);
                H.h[4] = __float2half_rn(v1.x * inv);
                H.h[5] = __float2half_rn(v1.y * inv);
                H.h[6] = __float2half_rn(v1.z * inv);
                H.h[7] = __float2half_rn(v1.w * inv);
                asm volatile("st.shared.v4.b32 [%0], {%1,%2,%3,%4};"
                             :: "r"(dst), "r"(H.q.x), "r"(H.q.y),
                                "r"(H.q.z), "r"(H.q.w) : "memory");
            }
            __syncthreads();
            #pragma unroll
            for (int ks = 0; ks < 4; ks++) {
                uint32_t aoff = ((uint32_t)(ks * 32) + aHi) ^ aXor;
                uint32_t boff = ((uint32_t)(ks * 32) + bHi) ^ bXor;
                uint32_t fa[2][4], fb[2][4];
                #pragma unroll
                for (int mi = 0; mi < 2; mi++)
                    LDSM4(fa[mi][0], fa[mi][1], fa[mi][2], fa[mi][3],
                          tAb + aRowOff + mi * 2048 + aoff);
                #pragma unroll
                for (int nj = 0; nj < 2; nj++)
                    LDSM4(fb[nj][0], fb[nj][1], fb[nj][2], fb[nj][3],
                          tBb + bRowOff + nj * 2048 + boff);
                #pragma unroll
                for (int mi = 0; mi < 2; mi++)
                    #pragma unroll
                    for (int nj = 0; nj < 2; nj++) {
                        HMMA16816(acc[mi][2 * nj],     fa[mi], fb[nj][0], fb[nj][1]);
                        HMMA16816(acc[mi][2 * nj + 1], fa[mi], fb[nj][2], fb[nj][3]);
                    }
            }
        }

        #pragma unroll
        for (int mi = 0; mi < 2; mi++) {
            const int r0 = wm + mi * 16 + (lid >> 2);
            float tAcc = 0.0f, sAcc = 0.0f, tBcc = 0.0f, sBcc = 0.0f;
            #pragma unroll
            for (int n8 = 0; n8 < 4; n8++) {
                #pragma unroll
                for (int j = 0; j < 2; j++) {
                    float lab = slab2[wn + n8 * 8 + 2 * (lid & 3) + j];
                    float g0 = gaussf(acc[mi][n8][j]);
                    tAcc += g0; sAcc += g0 * lab;
                    float g1 = gaussf(acc[mi][n8][2 + j]);
                    tBcc += g1; sBcc += g1 * lab;
                }
            }
            #pragma unroll
            for (int o = 1; o < 4; o <<= 1) {
                tAcc += __shfl_xor_sync(0xffffffffu, tAcc, o);
                sAcc += __shfl_xor_sync(0xffffffffu, sAcc, o);
                tBcc += __shfl_xor_sync(0xffffffffu, tBcc, o);
                sBcc += __shfl_xor_sync(0xffffffffu, sBcc, o);
            }
            if ((lid & 3) == 0) {
                if (mtile * 128 + r0 < F) {
                    int row = sgrow[r0];
                    atomicAdd(&g_ftot[row], tAcc);
                    atomicAdd(&g_fs1[row], sAcc);
                }
                if (mtile * 128 + r0 + 8 < F) {
                    int row = sgrow[r0 + 8];
                    atomicAdd(&g_ftot[row], tBcc);
                    atomicAdd(&g_fs1[row], sBcc);
                }
            }
        }
    }

    // ---- fused tier-1 rewrite + tier-2 flag (last block) ----
    __threadfence();
    __syncthreads();
    __shared__ int s_last;
    if (tid == 0) {
        int tk = atomicAdd(&g_ticket2, 1);
        s_last = (tk == (int)gridDim.x - 1) ? 1 : 0;
    }
    __syncthreads();
    if (s_last) {
        __threadfence();
        for (int i = tid; i < TEST_P; i += 256) {
            if (!g_flagged[i]) { g_flagged2[i] = 0; continue; }
            float tot = __ldcg(&g_ftot[i]);
            float s1v = __ldcg(&g_fs1[i]);
            float p0 = (tot - s1v) / tot, p1 = s1v / tot;
            write_row(out, out_size, i, p0, p1);
            int fl2 = (fabsf(p1 - p0) < TAU2) ? 1 : 0;
            g_flagged2[i] = fl2;
            if (fl2) {
                int idx = atomicAdd(&g_f2count, 1);
                g_f2list[idx] = i;
            }
        }
    }
}

// ---------------------------------------------------------------------------
// Kernel 4: exact fp32 recompute for tier-2 rows; last block rewrites them.
// ---------------------------------------------------------------------------
__global__ void fixup32_accum(const float* __restrict__ train,
                              const float* __restrict__ test,
                              const int* __restrict__ label,
                              float* __restrict__ out, int out_size) {
    __shared__ float sa[KDIM];
    int total = g_f2count * NSLICE;
    for (int w = blockIdx.x; w < total; w += gridDim.x) {
        int row   = g_f2list[w / NSLICE];
        int slice = w % NSLICE;
        float ivte = g_invte[row];
        __syncthreads();
        for (int i = threadIdx.x; i < KDIM; i += 256)
            sa[i] = test[(size_t)row * KDIM + i] * ivte;
        __syncthreads();
        int wid = threadIdx.x >> 5, lid = threadIdx.x & 31;
        float tot = 0.0f, s1 = 0.0f;
        for (int r = 0; r < 32; r++) {
            int trow = slice * 256 + wid * 32 + r;
            const float* brow = train + (size_t)trow * KDIM;
            float d = 0.0f;
            #pragma unroll 8
            for (int i = lid; i < KDIM; i += 32) d += sa[i] * brow[i];
            #pragma unroll
            for (int o = 16; o; o >>= 1) d += __shfl_xor_sync(0xffffffffu, d, o);
            if (lid == 0) {
                float dot = d * g_invtr[trow];
                float d2 = fmaxf(2.0f - 2.0f * dot, 0.0f);
                float g = __expf(-2.0f * sqrtf(d2));
                tot += g;
                s1  += g * (float)label[trow];
            }
        }
        if (lid == 0) {
            atomicAdd(&g_f2tot[row], tot);
            atomicAdd(&g_f2s1[row], s1);
        }
    }

    // ---- fused tier-2 rewrite (last block) ----
    __threadfence();
    __syncthreads();
    __shared__ int s_last;
    if (threadIdx.x == 0) {
        int tk = atomicAdd(&g_ticket3, 1);
        s_last = (tk == (int)gridDim.x - 1) ? 1 : 0;
    }
    __syncthreads();
    if (s_last) {
        __threadfence();
        for (int i = threadIdx.x; i < TEST_P; i += 256) {
            if (!g_flagged2[i]) continue;
            float tot = __ldcg(&g_f2tot[i]);
            float s1v = __ldcg(&g_f2s1[i]);
            write_row(out, out_size, i, (tot - s1v) / tot, s1v / tot);
        }
    }
}

extern "C" void kernel_launch(void* const* d_in, const int* in_sizes, int n_in,
                              void* d_out, int out_size) {
    const float* train = (const float*)d_in[0];
    const int*   label = (const int*)d_in[1];
    const float* test  = (const float*)d_in[2];

    cudaFuncSetAttribute(pnn_imma, cudaFuncAttributeMaxDynamicSharedMemorySize,
                         SMEM_TOTAL);

    prep_kernel<<<TRAIN_N + TEST_P, 256>>>(train, test);

    dim3 grid(TRAIN_N / NT, TEST_P / MT);   // (64, 32)
    pnn_imma<<<grid, THREADS, SMEM_TOTAL>>>(label, (float*)d_out, out_size);

    fixup16_kernel<<<256, 256>>>(train, test, label, (float*)d_out, out_size);
    fixup32_accum<<<256, 256>>>(train, test, label, (float*)d_out, out_size);
}

// round 14
// speedup vs baseline: 1.2226x; 1.2226x over previous
#include <cuda_runtime.h>
#include <cuda_fp16.h>
#include <cstdint>

// ---------------------------------------------------------------------------
// PNN_43095701848191 — build r14: exact R9 pipeline (best measured, 124.8us)
// with a latency-optimized prep (one warp per row, MLP=8/thread, no smem).
//
//  prep:     row L2 norms; per-row symmetric int8 quantization
//            (scale = maxabs/127); inverse norms. Warp-per-row, shuffle-only.
//  imma:     CTA 128x128 @ 256 thr (warp tile 32x64), 2 CTAs/SM, K-chunks of
//            128 s8 (SW128), 3-stage cp.async, mma.sync.m16n8k32.s8.
//            dot = (float)i32 * sa * sb is EXACT (|i32| < 2^24).
//            Epilogue: Gauss + per-class sums (atomics).
//  finalize: probs + argmax + write; flag |p1-p0| < 4e-4 -> tier-1 list.
//  fixup16:  gathered fp16 HMMA GEMM over tier-1 rows (f32->f16 on the fly).
//  f16write: rewrite tier-1 rows; flag |gap| < 1e-5 -> tier-2.
//  fixup32:  exact fp32 recompute of tier-2 rows; rewrite.
// ---------------------------------------------------------------------------

#define TRAIN_N 8192
#define TEST_P  4096
#define KDIM    1024

#define MT 128
#define NT 128
#define NCHUNK 8              // 8 chunks x 128 s8
#define STAGES 3
#define THREADS 256

#define TAU1 4e-4f
#define TAU2 1e-5f
#define NSLICE 32

__device__ __align__(16) uint32_t g_Aq[TEST_P * KDIM / 4];
__device__ __align__(16) uint32_t g_Bq[TRAIN_N * KDIM / 4];
__device__ float g_sa[TEST_P];
__device__ float g_sb[TRAIN_N];
__device__ float g_invte[TEST_P];
__device__ float g_invtr[TRAIN_N];
__device__ float g_tot[TEST_P];
__device__ float g_s1[TEST_P];
__device__ int   g_flagged[TEST_P];
__device__ int   g_flaglist[TEST_P];
__device__ int   g_flagcount;
__device__ float g_ftot[TEST_P];
__device__ float g_fs1[TEST_P];
__device__ int   g_flagged2[TEST_P];
__device__ int   g_f2list[TEST_P];
__device__ int   g_f2count;
__device__ float g_f2tot[TEST_P];
__device__ float g_f2s1[TEST_P];

__device__ __forceinline__ uint32_t smem_u32(const void* p) {
    uint32_t a;
    asm("{ .reg .u64 t; cvta.to.shared.u64 t, %1; cvt.u32.u64 %0, t; }"
        : "=r"(a) : "l"(p));
    return a;
}

#define SW128(o) ((o) ^ (((o) >> 3) & 0x70))

#define LDSM4(r0, r1, r2, r3, a) \
    asm volatile("ldmatrix.sync.aligned.m8n8.x4.shared.b16 {%0,%1,%2,%3}, [%4];" \
                 : "=r"(r0), "=r"(r1), "=r"(r2), "=r"(r3) : "r"(a))

#define IMMA16832(d, a, b0, b1) \
    asm volatile("mma.sync.aligned.m16n8k32.row.col.s32.s8.s8.s32 " \
                 "{%0,%1,%2,%3}, {%4,%5,%6,%7}, {%8,%9}, {%0,%1,%2,%3};" \
                 : "+r"((d)[0]), "+r"((d)[1]), "+r"((d)[2]), "+r"((d)[3]) \
                 : "r"((a)[0]), "r"((a)[1]), "r"((a)[2]), "r"((a)[3]), \
                   "r"(b0), "r"(b1))

#define HMMA16816(d, a, b0, b1) \
    asm volatile("mma.sync.aligned.m16n8k16.row.col.f32.f16.f16.f32 " \
                 "{%0,%1,%2,%3}, {%4,%5,%6,%7}, {%8,%9}, {%0,%1,%2,%3};" \
                 : "+f"((d)[0]), "+f"((d)[1]), "+f"((d)[2]), "+f"((d)[3]) \
                 : "r"((a)[0]), "r"((a)[1]), "r"((a)[2]), "r"((a)[3]), \
                   "r"(b0), "r"(b1))

#define EX2(out, in) asm("ex2.approx.f32 %0, %1;" : "=f"(out) : "f"(in))
#define GAUSS_C (-2.885390082f)   /* -2 * log2(e) */

__device__ __forceinline__ float gaussf(float dot) {
    float d2 = fmaxf(2.0f - 2.0f * dot, 0.0f);
    float d;
    asm("sqrt.approx.f32 %0, %1;" : "=f"(d) : "f"(d2));
    float g; EX2(g, GAUSS_C * d);
    return g;
}

// ---------------------------------------------------------------------------
// Kernel 1: warp-per-row norms + int8 quantization. 8 float4 loads per
// thread up front (MLP=8), warp-shuffle reduction only, no smem/barriers.
// ---------------------------------------------------------------------------
__global__ void prep_kernel(const float* __restrict__ train,
                            const float* __restrict__ test) {
    const int warp = blockIdx.x * 8 + (threadIdx.x >> 5);  // row 0..12287
    const int lane = threadIdx.x & 31;
    const bool isTrain = warp < TRAIN_N;
    const float* row = isTrain ? train + (size_t)warp * KDIM
                               : test + (size_t)(warp - TRAIN_N) * KDIM;

    float4 v[8];
    #pragma unroll
    for (int k = 0; k < 8; k++) v[k] = ((const float4*)row)[lane + 32 * k];

    float s = 0.0f, m = 0.0f;
    #pragma unroll
    for (int k = 0; k < 8; k++) {
        s += v[k].x * v[k].x + v[k].y * v[k].y + v[k].z * v[k].z + v[k].w * v[k].w;
        m = fmaxf(m, fmaxf(fmaxf(fabsf(v[k].x), fabsf(v[k].y)),
                           fmaxf(fabsf(v[k].z), fabsf(v[k].w))));
    }
    #pragma unroll
    for (int o = 16; o; o >>= 1) {
        s += __shfl_xor_sync(0xffffffffu, s, o);
        m = fmaxf(m, __shfl_xor_sync(0xffffffffu, m, o));
    }
    const float inv = rsqrtf(s);
    const float maxn = m * inv;
    const float qs = 127.0f / maxn;

    uint32_t* dstq = isTrain ? g_Bq + (size_t)warp * 256
                             : g_Aq + (size_t)(warp - TRAIN_N) * 256;
    #pragma unroll
    for (int k = 0; k < 8; k++) {
        int q0 = __float2int_rn(v[k].x * inv * qs);
        int q1 = __float2int_rn(v[k].y * inv * qs);
        int q2 = __float2int_rn(v[k].z * inv * qs);
        int q3 = __float2int_rn(v[k].w * inv * qs);
        dstq[lane + 32 * k] =
            (uint32_t)(q0 & 255) | ((uint32_t)(q1 & 255) << 8) |
            ((uint32_t)(q2 & 255) << 16) | ((uint32_t)(q3 & 255) << 24);
    }

    if (lane == 0) {
        if (isTrain) {
            g_invtr[warp] = inv;
            g_sb[warp] = maxn * (1.0f / 127.0f);
        } else {
            int bi = warp - TRAIN_N;
            g_invte[bi] = inv;
            g_sa[bi] = maxn * (1.0f / 127.0f);
            g_tot[bi] = 0.0f;
            g_s1[bi] = 0.0f;
        }
        if (warp == 0) { g_flagcount = 0; g_f2count = 0; }
    }
}

// ---------------------------------------------------------------------------
// Kernel 2: int8 IMMA GEMM, 128x128 tile, 256 threads, 2 CTAs/SM (R9 config).
// ---------------------------------------------------------------------------
#define SLAB_OFF  0
#define SSB_OFF   512
#define SSA_OFF   1024
#define TILES_OFF 2048
#define STAGE_BYTES (MT * 128 + NT * 128)   // 32768
#define B_OFF       (MT * 128)              // 16384
#define SMEM_TOTAL  (TILES_OFF + STAGES * STAGE_BYTES)  // 100352

__device__ __forceinline__ void load_chunk(int tid, uint32_t sb, int stage,
                                           const char* gA, const char* gB,
                                           int chunk) {
    uint32_t base = sb + TILES_OFF + (uint32_t)stage * STAGE_BYTES;
    const char* srcA = gA + (size_t)chunk * 128;
    const char* srcB = gB + (size_t)chunk * 128;
    #pragma unroll
    for (int i = 0; i < 8; i++) {
        int u = tid + THREADS * i;
        const char* src;
        uint32_t dst;
        if (u < 1024) {                 // A tile: 128 rows x 128 B
            int r = u >> 3, c = u & 7;
            src = srcA + (size_t)r * KDIM + c * 16;
            dst = base + SW128((uint32_t)(r * 128 + c * 16));
        } else {                        // B tile: 128 rows x 128 B
            int vv = u - 1024;
            int r = vv >> 3, c = vv & 7;
            src = srcB + (size_t)r * KDIM + c * 16;
            dst = base + B_OFF + SW128((uint32_t)(r * 128 + c * 16));
        }
        asm volatile("cp.async.cg.shared.global [%0], [%1], 16;"
                     :: "r"(dst), "l"(src));
    }
    asm volatile("cp.async.commit_group;" ::: "memory");
}

__global__ __launch_bounds__(THREADS, 2)
void pnn_imma(const int* __restrict__ label) {
    extern __shared__ __align__(1024) char smem[];
    uint32_t sb = smem_u32(smem);
    const int tid = threadIdx.x;
    const int wid = tid >> 5, lid = tid & 31;
    const int rowBase = blockIdx.y * MT;      // test rows
    const int colBase = blockIdx.x * NT;      // train rows

    float* slab = (float*)(smem + SLAB_OFF);
    float* ssb  = (float*)(smem + SSB_OFF);
    float* ssa  = (float*)(smem + SSA_OFF);
    if (tid < NT)          slab[tid] = (float)label[colBase + tid];
    else if (tid < 2 * NT) ssb[tid - NT] = g_sb[colBase + tid - NT];
    if (tid < MT)          ssa[tid] = g_sa[rowBase + tid];

    const char* gA = (const char*)g_Aq + (size_t)rowBase * KDIM;
    const char* gB = (const char*)g_Bq + (size_t)colBase * KDIM;

    // warp layout: 4 (m) x 2 (n); warp tile 32 x 64
    const int wm = (wid >> 1) * 32;
    const int wn = (wid & 1) * 64;

    const int aRow = wm + (lid & 15);
    const uint32_t aXor = (uint32_t)((aRow & 7) << 4);
    const uint32_t aHi  = (uint32_t)(((lid >> 4) & 1) << 4);
    const uint32_t aRowOff = (uint32_t)(aRow * 128);
    const int bRow = wn + (lid & 7) + (((lid >> 4) & 1) << 3);
    const uint32_t bXor = (uint32_t)((bRow & 7) << 4);
    const uint32_t bHi  = (uint32_t)(((lid >> 3) & 1) << 4);
    const uint32_t bRowOff = (uint32_t)(bRow * 128);

    int acc[2][8][4];
    #pragma unroll
    for (int mi = 0; mi < 2; mi++)
        #pragma unroll
        for (int n = 0; n < 8; n++)
            #pragma unroll
            for (int c = 0; c < 4; c++) acc[mi][n][c] = 0;

    load_chunk(tid, sb, 0, gA, gB, 0);
    load_chunk(tid, sb, 1, gA, gB, 1);

    #pragma unroll 1
    for (int t = 0; t < NCHUNK; t++) {
        if (t + 1 < NCHUNK) {
            asm volatile("cp.async.wait_group 1;" ::: "memory");
        } else {
            asm volatile("cp.async.wait_group 0;" ::: "memory");
        }
        __syncthreads();
        if (t + 2 < NCHUNK)
            load_chunk(tid, sb, (t + 2) % STAGES, gA, gB, t + 2);

        const uint32_t base = sb + TILES_OFF + (uint32_t)(t % STAGES) * STAGE_BYTES;
        #pragma unroll
        for (int ks = 0; ks < 4; ks++) {
            uint32_t aoff = ((uint32_t)(ks * 32) + aHi) ^ aXor;
            uint32_t boff = ((uint32_t)(ks * 32) + bHi) ^ bXor;
            uint32_t fa[2][4], fb[4][4];
            #pragma unroll
            for (int mi = 0; mi < 2; mi++)
                LDSM4(fa[mi][0], fa[mi][1], fa[mi][2], fa[mi][3],
                      base + aRowOff + mi * 2048 + aoff);
            #pragma unroll
            for (int nj = 0; nj < 4; nj++)
                LDSM4(fb[nj][0], fb[nj][1], fb[nj][2], fb[nj][3],
                      base + B_OFF + bRowOff + nj * 2048 + boff);
            #pragma unroll
            for (int mi = 0; mi < 2; mi++)
                #pragma unroll
                for (int nj = 0; nj < 4; nj++) {
                    IMMA16832(acc[mi][2 * nj],     fa[mi], fb[nj][0], fb[nj][1]);
                    IMMA16832(acc[mi][2 * nj + 1], fa[mi], fb[nj][2], fb[nj][3]);
                }
        }
    }

    // ---- epilogue: i32 -> scaled fp32 dot (exact) -> Gauss -> class sums ----
    #pragma unroll
    for (int mi = 0; mi < 2; mi++) {
        const int r0 = wm + mi * 16 + (lid >> 2);
        const float sa0 = ssa[r0];
        const float sa1 = ssa[r0 + 8];
        float tA = 0.0f, sA = 0.0f, tB = 0.0f, sB = 0.0f;
        #pragma unroll
        for (int n8 = 0; n8 < 8; n8++) {
            #pragma unroll
            for (int j = 0; j < 2; j++) {
                const int col = wn + n8 * 8 + 2 * (lid & 3) + j;
                const float lab = slab[col];
                const float sbv = ssb[col];
                {
                    float g = gaussf((float)acc[mi][n8][j] * (sa0 * sbv));
                    tA += g; sA += g * lab;
                }
                {
                    float g = gaussf((float)acc[mi][n8][2 + j] * (sa1 * sbv));
                    tB += g; sB += g * lab;
                }
            }
        }
        #pragma unroll
        for (int o = 1; o < 4; o <<= 1) {
            tA += __shfl_xor_sync(0xffffffffu, tA, o);
            sA += __shfl_xor_sync(0xffffffffu, sA, o);
            tB += __shfl_xor_sync(0xffffffffu, tB, o);
            sB += __shfl_xor_sync(0xffffffffu, sB, o);
        }
        if ((lid & 3) == 0) {
            int rowA = rowBase + r0;
            atomicAdd(&g_tot[rowA], tA);
            atomicAdd(&g_s1[rowA], sA);
            atomicAdd(&g_tot[rowA + 8], tB);
            atomicAdd(&g_s1[rowA + 8], sB);
        }
    }
}

// ---------------------------------------------------------------------------
// Kernel 3: probs + argmax + write; tier-1 flag.
// ---------------------------------------------------------------------------
__device__ __forceinline__ void write_row(float* out, int out_size, int i,
                                          float p0, float p1) {
    float res = (p1 > p0) ? 1.0f : 0.0f;
    if (out_size >= TEST_P * 3) {
        out[i] = res;
        out[TEST_P + 2 * i]     = p0;
        out[TEST_P + 2 * i + 1] = p1;
    } else if (out_size == TEST_P * 2) {
        out[2 * i] = p0;
        out[2 * i + 1] = p1;
    } else {
        out[i] = res;
    }
}

__global__ void finalize_kernel(float* __restrict__ out, int out_size) {
    int i = blockIdx.x * blockDim.x + threadIdx.x;
    if (i >= TEST_P) return;
    float tot = g_tot[i], s1 = g_s1[i];
    float p0 = (tot - s1) / tot, p1 = s1 / tot;
    write_row(out, out_size, i, p0, p1);
    int fl = (fabsf(p1 - p0) < TAU1) ? 1 : 0;
    g_flagged[i] = fl;
    g_ftot[i] = 0.0f;
    g_fs1[i] = 0.0f;
    if (fl) {
        int idx = atomicAdd(&g_flagcount, 1);
        g_flaglist[idx] = i;
    }
}

// ---------------------------------------------------------------------------
// Kernel 4: gathered fp16 HMMA GEMM over tier-1 rows; f32 -> f16 on the fly.
// Unit = (128-row mtile, 64-col ntile), full K.
// ---------------------------------------------------------------------------
__global__ __launch_bounds__(256)
void fixup16_kernel(const float* __restrict__ train,
                    const float* __restrict__ test,
                    const int* __restrict__ label) {
    __shared__ int sgrow[128];
    __shared__ float sinvA[128];
    __shared__ float sinvB[64];
    __shared__ float slab2[64];
    __shared__ __align__(1024) char tA[16384];   // 128 rows x 128 B (f16)
    __shared__ __align__(1024) char tB[8192];    // 64 rows x 128 B (f16)

    const int F = g_flagcount;
    if (F == 0) return;
    const int numM = (F + 127) / 128;
    const int total = numM * 128;                // 128 ntiles of 64 cols
    const int tid = threadIdx.x;
    const int wid = tid >> 5, lid = tid & 31;
    const uint32_t tAb = smem_u32(tA), tBb = smem_u32(tB);

    const int wm = (wid >> 1) * 32;
    const int wn = (wid & 1) * 32;
    const int aRow = wm + (lid & 15);
    const uint32_t aXor = (uint32_t)((aRow & 7) << 4);
    const uint32_t aHi  = (uint32_t)(((lid >> 4) & 1) << 4);
    const uint32_t aRowOff = (uint32_t)(aRow * 128);
    const int bRow = wn + (lid & 7) + (((lid >> 4) & 1) << 3);
    const uint32_t bXor = (uint32_t)((bRow & 7) << 4);
    const uint32_t bHi  = (uint32_t)(((lid >> 3) & 1) << 4);
    const uint32_t bRowOff = (uint32_t)(bRow * 128);

    for (int u = blockIdx.x; u < total; u += gridDim.x) {
        const int mtile = u >> 7;
        const int ntile = u & 127;
        const int colBase = ntile * 64;
        __syncthreads();
        if (tid < 128) {
            int gi = mtile * 128 + tid;
            int row = (gi < F) ? g_flaglist[gi] : 0;
            sgrow[tid] = row;
            sinvA[tid] = g_invte[row];
        } else if (tid < 192) {
            slab2[tid - 128] = (float)label[colBase + tid - 128];
            sinvB[tid - 128] = g_invtr[colBase + tid - 128];
        }
        __syncthreads();

        float acc[2][4][4];
        #pragma unroll
        for (int mi = 0; mi < 2; mi++)
            #pragma unroll
            for (int n = 0; n < 4; n++)
                #pragma unroll
                for (int cc = 0; cc < 4; cc++) acc[mi][n][cc] = 0.0f;

        #pragma unroll 1
        for (int chunk = 0; chunk < 16; chunk++) {
            __syncthreads();
            #pragma unroll
            for (int i = 0; i < 6; i++) {
                int u2 = tid + 256 * i;
                int r, cc;
                const float* src;
                float inv;
                uint32_t dst;
                if (u2 < 1024) {
                    r = u2 >> 3; cc = u2 & 7;
                    src = test + (size_t)sgrow[r] * KDIM + chunk * 64 + cc * 8;
                    inv = sinvA[r];
                    dst = tAb + SW128((uint32_t)(r * 128 + cc * 16));
                } else {
                    int vv = u2 - 1024;
                    r = vv >> 3; cc = vv & 7;
                    src = train + (size_t)(colBase + r) * KDIM + chunk * 64 + cc * 8;
                    inv = sinvB[r];
                    dst = tBb + SW128((uint32_t)(r * 128 + cc * 16));
                }
                float4 v0 = ((const float4*)src)[0];
                float4 v1 = ((const float4*)src)[1];
                union { __half h[8]; uint4 q; } H;
                H.h[0] = __float2half_rn(v0.x * inv);
                H.h[1] = __float2half_rn(v0.y * inv);
                H.h[2] = __float2half_rn(v0.z * inv);
                H.h[3] = __float2half_rn(v0.w * inv);
                H.h[4] = __float2half_rn(v1.x * inv);
                H.h[5] = __float2half_rn(v1.y * inv);
                H.h[6] = __float2half_rn(v1.z * inv);
                H.h[7] = __float2half_rn(v1.w * inv);
                asm volatile("st.shared.v4.b32 [%0], {%1,%2,%3,%4};"
                             :: "r"(dst), "r"(H.q.x), "r"(H.q.y),
                                "r"(H.q.z), "r"(H.q.w) : "memory");
            }
            __syncthreads();
            #pragma unroll
            for (int ks = 0; ks < 4; ks++) {
                uint32_t aoff = ((uint32_t)(ks * 32) + aHi) ^ aXor;
                uint32_t boff = ((uint32_t)(ks * 32) + bHi) ^ bXor;
                uint32_t fa[2][4], fb[2][4];
                #pragma unroll
                for (int mi = 0; mi < 2; mi++)
                    LDSM4(fa[mi][0], fa[mi][1], fa[mi][2], fa[mi][3],
                          tAb + aRowOff + mi * 2048 + aoff);
                #pragma unroll
                for (int nj = 0; nj < 2; nj++)
                    LDSM4(fb[nj][0], fb[nj][1], fb[nj][2], fb[nj][3],
                          tBb + bRowOff + nj * 2048 + boff);
                #pragma unroll
                for (int mi = 0; mi < 2; mi++)
                    #pragma unroll
                    for (int nj = 0; nj < 2; nj++) {
                        HMMA16816(acc[mi][2 * nj],     fa[mi], fb[nj][0], fb[nj][1]);
                        HMMA16816(acc[mi][2 * nj + 1], fa[mi], fb[nj][2], fb[nj][3]);
                    }
            }
        }

        #pragma unroll
        for (int mi = 0; mi < 2; mi++) {
            const int r0 = wm + mi * 16 + (lid >> 2);
            float tAcc = 0.0f, sAcc = 0.0f, tBcc = 0.0f, sBcc = 0.0f;
            #pragma unroll
            for (int n8 = 0; n8 < 4; n8++) {
                #pragma unroll
                for (int j = 0; j < 2; j++) {
                    float lab = slab2[wn + n8 * 8 + 2 * (lid & 3) + j];
                    float g0 = gaussf(acc[mi][n8][j]);
                    tAcc += g0; sAcc += g0 * lab;
                    float g1 = gaussf(acc[mi][n8][2 + j]);
                    tBcc += g1; sBcc += g1 * lab;
                }
            }
            #pragma unroll
            for (int o = 1; o < 4; o <<= 1) {
                tAcc += __shfl_xor_sync(0xffffffffu, tAcc, o);
                sAcc += __shfl_xor_sync(0xffffffffu, sAcc, o);
                tBcc += __shfl_xor_sync(0xffffffffu, tBcc, o);
                sBcc += __shfl_xor_sync(0xffffffffu, sBcc, o);
            }
            if ((lid & 3) == 0) {
                if (mtile * 128 + r0 < F) {
                    int row = sgrow[r0];
                    atomicAdd(&g_ftot[row], tAcc);
                    atomicAdd(&g_fs1[row], sAcc);
                }
                if (mtile * 128 + r0 + 8 < F) {
                    int row = sgrow[r0 + 8];
                    atomicAdd(&g_ftot[row], tBcc);
                    atomicAdd(&g_fs1[row], sBcc);
                }
            }
        }
    }
}

// ---------------------------------------------------------------------------
// Kernel 5: rewrite tier-1 rows from fp16 sums; tier-2 flag.
// ---------------------------------------------------------------------------
__global__ void fixup16_write(float* __restrict__ out, int out_size) {
    int i = blockIdx.x * blockDim.x + threadIdx.x;
    if (i >= TEST_P) return;
    if (!g_flagged[i]) { g_flagged2[i] = 0; return; }
    float tot = g_ftot[i], s1 = g_fs1[i];
    float p0 = (tot - s1) / tot, p1 = s1 / tot;
    write_row(out, out_size, i, p0, p1);
    int fl2 = (fabsf(p1 - p0) < TAU2) ? 1 : 0;
    g_flagged2[i] = fl2;
    if (fl2) {
        int idx = atomicAdd(&g_f2count, 1);
        g_f2list[idx] = i;
        g_f2tot[i] = 0.0f;
        g_f2s1[i] = 0.0f;
    }
}

// ---------------------------------------------------------------------------
// Kernel 6: exact fp32 recompute for tier-2 rows.
// ---------------------------------------------------------------------------
__global__ void fixup32_accum(const float* __restrict__ train,
                              const float* __restrict__ test,
                              const int* __restrict__ label) {
    __shared__ float sa[KDIM];
    int total = g_f2count * NSLICE;
    for (int w = blockIdx.x; w < total; w += gridDim.x) {
        int row   = g_f2list[w / NSLICE];
        int slice = w % NSLICE;
        float ivte = g_invte[row];
        __syncthreads();
        for (int i = threadIdx.x; i < KDIM; i += 256)
            sa[i] = test[(size_t)row * KDIM + i] * ivte;
        __syncthreads();
        int wid = threadIdx.x >> 5, lid = threadIdx.x & 31;
        float tot = 0.0f, s1 = 0.0f;
        for (int r = 0; r < 32; r++) {
            int trow = slice * 256 + wid * 32 + r;
            const float* brow = train + (size_t)trow * KDIM;
            float d = 0.0f;
            #pragma unroll 8
            for (int i = lid; i < KDIM; i += 32) d += sa[i] * brow[i];
            #pragma unroll
            for (int o = 16; o; o >>= 1) d += __shfl_xor_sync(0xffffffffu, d, o);
            if (lid == 0) {
                float dot = d * g_invtr[trow];
                float d2 = fmaxf(2.0f - 2.0f * dot, 0.0f);
                float g = __expf(-2.0f * sqrtf(d2));
                tot += g;
                s1  += g * (float)label[trow];
            }
        }
        if (lid == 0) {
            atomicAdd(&g_f2tot[row], tot);
            atomicAdd(&g_f2s1[row], s1);
        }
    }
}

__global__ void fixup32_write(float* __restrict__ out, int out_size) {
    int i = blockIdx.x * blockDim.x + threadIdx.x;
    if (i >= TEST_P || !g_flagged2[i]) return;
    float tot = g_f2tot[i], s1 = g_f2s1[i];
    write_row(out, out_size, i, (tot - s1) / tot, s1 / tot);
}

extern "C" void kernel_launch(void* const* d_in, const int* in_sizes, int n_in,
                              void* d_out, int out_size) {
    const float* train = (const float*)d_in[0];
    const int*   label = (const int*)d_in[1];
    const float* test  = (const float*)d_in[2];

    cudaFuncSetAttribute(pnn_imma, cudaFuncAttributeMaxDynamicSharedMemorySize,
                         SMEM_TOTAL);

    prep_kernel<<<(TRAIN_N + TEST_P) / 8, 256>>>(train, test);

    dim3 grid(TRAIN_N / NT, TEST_P / MT);   // (64, 32)
    pnn_imma<<<grid, THREADS, SMEM_TOTAL>>>(label);

    finalize_kernel<<<(TEST_P + 255) / 256, 256>>>((float*)d_out, out_size);
    fixup16_kernel<<<256, 256>>>(train, test, label);
    fixup16_write<<<(TEST_P + 255) / 256, 256>>>((float*)d_out, out_size);
    fixup32_accum<<<256, 256>>>(train, test, label);
    fixup32_write<<<(TEST_P + 255) / 256, 256>>>((float*)d_out, out_size);
}

// round 15
// speedup vs baseline: 1.2250x; 1.0019x over previous
#include <cuda_runtime.h>
#include <cuda_fp16.h>
#include <cstdint>

// ---------------------------------------------------------------------------
// PNN_43095701848191 — build r15: R14 (117.0us) + write-kernels folded into
// their producers' LAST BLOCK with O(flag-count) serial work (the R13 failure
// was O(4096) serial scans; these scan only the compact lists).
//
//  prep:     warp-per-row norms + int8 quantization (MLP=8, shuffle-only).
//  imma:     CTA 128x128 @ 256 thr (warp tile 32x64), 2 CTAs/SM, 8 K-chunks
//            of 128 s8 (SW128), 3-stage cp.async, mma.sync.m16n8k32.s8.
//  finalize: probs + argmax + write (parallel, 4096 rows); tier-1 flag.
//  fixup16:  gathered fp16 HMMA GEMM over tier-1 rows; last block rewrites
//            the F tier-1 rows + flags tier-2 (|gap| < 1e-5).
//  fixup32:  exact fp32 recompute of tier-2 rows; last block rewrites them.
// ---------------------------------------------------------------------------

#define TRAIN_N 8192
#define TEST_P  4096
#define KDIM    1024

#define MT 128
#define NT 128
#define NCHUNK 8              // 8 chunks x 128 s8
#define STAGES 3
#define THREADS 256

#define TAU1 4e-4f
#define TAU2 1e-5f
#define NSLICE 32

__device__ __align__(16) uint32_t g_Aq[TEST_P * KDIM / 4];
__device__ __align__(16) uint32_t g_Bq[TRAIN_N * KDIM / 4];
__device__ float g_sa[TEST_P];
__device__ float g_sb[TRAIN_N];
__device__ float g_invte[TEST_P];
__device__ float g_invtr[TRAIN_N];
__device__ float g_tot[TEST_P];
__device__ float g_s1[TEST_P];
__device__ int   g_flaglist[TEST_P];
__device__ int   g_flagcount;
__device__ float g_ftot[TEST_P];
__device__ float g_fs1[TEST_P];
__device__ int   g_f2list[TEST_P];
__device__ int   g_f2count;
__device__ float g_f2tot[TEST_P];
__device__ float g_f2s1[TEST_P];
__device__ int   g_ticketA, g_ticketB;

__device__ __forceinline__ uint32_t smem_u32(const void* p) {
    uint32_t a;
    asm("{ .reg .u64 t; cvta.to.shared.u64 t, %1; cvt.u32.u64 %0, t; }"
        : "=r"(a) : "l"(p));
    return a;
}

#define SW128(o) ((o) ^ (((o) >> 3) & 0x70))

#define LDSM4(r0, r1, r2, r3, a) \
    asm volatile("ldmatrix.sync.aligned.m8n8.x4.shared.b16 {%0,%1,%2,%3}, [%4];" \
                 : "=r"(r0), "=r"(r1), "=r"(r2), "=r"(r3) : "r"(a))

#define IMMA16832(d, a, b0, b1) \
    asm volatile("mma.sync.aligned.m16n8k32.row.col.s32.s8.s8.s32 " \
                 "{%0,%1,%2,%3}, {%4,%5,%6,%7}, {%8,%9}, {%0,%1,%2,%3};" \
                 : "+r"((d)[0]), "+r"((d)[1]), "+r"((d)[2]), "+r"((d)[3]) \
                 : "r"((a)[0]), "r"((a)[1]), "r"((a)[2]), "r"((a)[3]), \
                   "r"(b0), "r"(b1))

#define HMMA16816(d, a, b0, b1) \
    asm volatile("mma.sync.aligned.m16n8k16.row.col.f32.f16.f16.f32 " \
                 "{%0,%1,%2,%3}, {%4,%5,%6,%7}, {%8,%9}, {%0,%1,%2,%3};" \
                 : "+f"((d)[0]), "+f"((d)[1]), "+f"((d)[2]), "+f"((d)[3]) \
                 : "r"((a)[0]), "r"((a)[1]), "r"((a)[2]), "r"((a)[3]), \
                   "r"(b0), "r"(b1))

#define EX2(out, in) asm("ex2.approx.f32 %0, %1;" : "=f"(out) : "f"(in))
#define GAUSS_C (-2.885390082f)   /* -2 * log2(e) */

__device__ __forceinline__ float gaussf(float dot) {
    float d2 = fmaxf(2.0f - 2.0f * dot, 0.0f);
    float d;
    asm("sqrt.approx.f32 %0, %1;" : "=f"(d) : "f"(d2));
    float g; EX2(g, GAUSS_C * d);
    return g;
}

__device__ __forceinline__ void write_row(float* out, int out_size, int i,
                                          float p0, float p1) {
    float res = (p1 > p0) ? 1.0f : 0.0f;
    if (out_size >= TEST_P * 3) {
        out[i] = res;
        out[TEST_P + 2 * i]     = p0;
        out[TEST_P + 2 * i + 1] = p1;
    } else if (out_size == TEST_P * 2) {
        out[2 * i] = p0;
        out[2 * i + 1] = p1;
    } else {
        out[i] = res;
    }
}

// ---------------------------------------------------------------------------
// Kernel 1: warp-per-row norms + int8 quantization (MLP=8, no smem).
// ---------------------------------------------------------------------------
__global__ void prep_kernel(const float* __restrict__ train,
                            const float* __restrict__ test) {
    const int warp = blockIdx.x * 8 + (threadIdx.x >> 5);  // row 0..12287
    const int lane = threadIdx.x & 31;
    const bool isTrain = warp < TRAIN_N;
    const float* row = isTrain ? train + (size_t)warp * KDIM
                               : test + (size_t)(warp - TRAIN_N) * KDIM;

    float4 v[8];
    #pragma unroll
    for (int k = 0; k < 8; k++) v[k] = ((const float4*)row)[lane + 32 * k];

    float s = 0.0f, m = 0.0f;
    #pragma unroll
    for (int k = 0; k < 8; k++) {
        s += v[k].x * v[k].x + v[k].y * v[k].y + v[k].z * v[k].z + v[k].w * v[k].w;
        m = fmaxf(m, fmaxf(fmaxf(fabsf(v[k].x), fabsf(v[k].y)),
                           fmaxf(fabsf(v[k].z), fabsf(v[k].w))));
    }
    #pragma unroll
    for (int o = 16; o; o >>= 1) {
        s += __shfl_xor_sync(0xffffffffu, s, o);
        m = fmaxf(m, __shfl_xor_sync(0xffffffffu, m, o));
    }
    const float inv = rsqrtf(s);
    const float maxn = m * inv;
    const float qs = 127.0f / maxn;

    uint32_t* dstq = isTrain ? g_Bq + (size_t)warp * 256
                             : g_Aq + (size_t)(warp - TRAIN_N) * 256;
    #pragma unroll
    for (int k = 0; k < 8; k++) {
        int q0 = __float2int_rn(v[k].x * inv * qs);
        int q1 = __float2int_rn(v[k].y * inv * qs);
        int q2 = __float2int_rn(v[k].z * inv * qs);
        int q3 = __float2int_rn(v[k].w * inv * qs);
        dstq[lane + 32 * k] =
            (uint32_t)(q0 & 255) | ((uint32_t)(q1 & 255) << 8) |
            ((uint32_t)(q2 & 255) << 16) | ((uint32_t)(q3 & 255) << 24);
    }

    if (lane == 0) {
        if (isTrain) {
            g_invtr[warp] = inv;
            g_sb[warp] = maxn * (1.0f / 127.0f);
        } else {
            int bi = warp - TRAIN_N;
            g_invte[bi] = inv;
            g_sa[bi] = maxn * (1.0f / 127.0f);
            g_tot[bi] = 0.0f;
            g_s1[bi] = 0.0f;
        }
        if (warp == 0) {
            g_flagcount = 0; g_f2count = 0;
            g_ticketA = 0; g_ticketB = 0;
        }
    }
}

// ---------------------------------------------------------------------------
// Kernel 2: int8 IMMA GEMM, 128x128 tile, 256 threads, 2 CTAs/SM.
// ---------------------------------------------------------------------------
#define SLAB_OFF  0
#define SSB_OFF   512
#define SSA_OFF   1024
#define TILES_OFF 2048
#define STAGE_BYTES (MT * 128 + NT * 128)   // 32768
#define B_OFF       (MT * 128)              // 16384
#define SMEM_TOTAL  (TILES_OFF + STAGES * STAGE_BYTES)  // 100352

__device__ __forceinline__ void load_chunk(int tid, uint32_t sb, int stage,
                                           const char* gA, const char* gB,
                                           int chunk) {
    uint32_t base = sb + TILES_OFF + (uint32_t)stage * STAGE_BYTES;
    const char* srcA = gA + (size_t)chunk * 128;
    const char* srcB = gB + (size_t)chunk * 128;
    #pragma unroll
    for (int i = 0; i < 8; i++) {
        int u = tid + THREADS * i;
        const char* src;
        uint32_t dst;
        if (u < 1024) {                 // A tile: 128 rows x 128 B
            int r = u >> 3, c = u & 7;
            src = srcA + (size_t)r * KDIM + c * 16;
            dst = base + SW128((uint32_t)(r * 128 + c * 16));
        } else {                        // B tile: 128 rows x 128 B
            int vv = u - 1024;
            int r = vv >> 3, c = vv & 7;
            src = srcB + (size_t)r * KDIM + c * 16;
            dst = base + B_OFF + SW128((uint32_t)(r * 128 + c * 16));
        }
        asm volatile("cp.async.cg.shared.global [%0], [%1], 16;"
                     :: "r"(dst), "l"(src));
    }
    asm volatile("cp.async.commit_group;" ::: "memory");
}

__global__ __launch_bounds__(THREADS, 2)
void pnn_imma(const int* __restrict__ label) {
    extern __shared__ __align__(1024) char smem[];
    uint32_t sb = smem_u32(smem);
    const int tid = threadIdx.x;
    const int wid = tid >> 5, lid = tid & 31;
    const int rowBase = blockIdx.y * MT;      // test rows
    const int colBase = blockIdx.x * NT;      // train rows

    float* slab = (float*)(smem + SLAB_OFF);
    float* ssb  = (float*)(smem + SSB_OFF);
    float* ssa  = (float*)(smem + SSA_OFF);
    if (tid < NT)          slab[tid] = (float)label[colBase + tid];
    else if (tid < 2 * NT) ssb[tid - NT] = g_sb[colBase + tid - NT];
    if (tid < MT)          ssa[tid] = g_sa[rowBase + tid];

    const char* gA = (const char*)g_Aq + (size_t)rowBase * KDIM;
    const char* gB = (const char*)g_Bq + (size_t)colBase * KDIM;

    // warp layout: 4 (m) x 2 (n); warp tile 32 x 64
    const int wm = (wid >> 1) * 32;
    const int wn = (wid & 1) * 64;

    const int aRow = wm + (lid & 15);
    const uint32_t aXor = (uint32_t)((aRow & 7) << 4);
    const uint32_t aHi  = (uint32_t)(((lid >> 4) & 1) << 4);
    const uint32_t aRowOff = (uint32_t)(aRow * 128);
    const int bRow = wn + (lid & 7) + (((lid >> 4) & 1) << 3);
    const uint32_t bXor = (uint32_t)((bRow & 7) << 4);
    const uint32_t bHi  = (uint32_t)(((lid >> 3) & 1) << 4);
    const uint32_t bRowOff = (uint32_t)(bRow * 128);

    int acc[2][8][4];
    #pragma unroll
    for (int mi = 0; mi < 2; mi++)
        #pragma unroll
        for (int n = 0; n < 8; n++)
            #pragma unroll
            for (int c = 0; c < 4; c++) acc[mi][n][c] = 0;

    load_chunk(tid, sb, 0, gA, gB, 0);
    load_chunk(tid, sb, 1, gA, gB, 1);

    #pragma unroll 1
    for (int t = 0; t < NCHUNK; t++) {
        if (t + 1 < NCHUNK) {
            asm volatile("cp.async.wait_group 1;" ::: "memory");
        } else {
            asm volatile("cp.async.wait_group 0;" ::: "memory");
        }
        __syncthreads();
        if (t + 2 < NCHUNK)
            load_chunk(tid, sb, (t + 2) % STAGES, gA, gB, t + 2);

        const uint32_t base = sb + TILES_OFF + (uint32_t)(t % STAGES) * STAGE_BYTES;
        #pragma unroll
        for (int ks = 0; ks < 4; ks++) {
            uint32_t aoff = ((uint32_t)(ks * 32) + aHi) ^ aXor;
            uint32_t boff = ((uint32_t)(ks * 32) + bHi) ^ bXor;
            uint32_t fa[2][4], fb[4][4];
            #pragma unroll
            for (int mi = 0; mi < 2; mi++)
                LDSM4(fa[mi][0], fa[mi][1], fa[mi][2], fa[mi][3],
                      base + aRowOff + mi * 2048 + aoff);
            #pragma unroll
            for (int nj = 0; nj < 4; nj++)
                LDSM4(fb[nj][0], fb[nj][1], fb[nj][2], fb[nj][3],
                      base + B_OFF + bRowOff + nj * 2048 + boff);
            #pragma unroll
            for (int mi = 0; mi < 2; mi++)
                #pragma unroll
                for (int nj = 0; nj < 4; nj++) {
                    IMMA16832(acc[mi][2 * nj],     fa[mi], fb[nj][0], fb[nj][1]);
                    IMMA16832(acc[mi][2 * nj + 1], fa[mi], fb[nj][2], fb[nj][3]);
                }
        }
    }

    // ---- epilogue: i32 -> scaled fp32 dot (exact) -> Gauss -> class sums ----
    #pragma unroll
    for (int mi = 0; mi < 2; mi++) {
        const int r0 = wm + mi * 16 + (lid >> 2);
        const float sa0 = ssa[r0];
        const float sa1 = ssa[r0 + 8];
        float tA = 0.0f, sA = 0.0f, tB = 0.0f, sB = 0.0f;
        #pragma unroll
        for (int n8 = 0; n8 < 8; n8++) {
            #pragma unroll
            for (int j = 0; j < 2; j++) {
                const int col = wn + n8 * 8 + 2 * (lid & 3) + j;
                const float lab = slab[col];
                const float sbv = ssb[col];
                {
                    float g = gaussf((float)acc[mi][n8][j] * (sa0 * sbv));
                    tA += g; sA += g * lab;
                }
                {
                    float g = gaussf((float)acc[mi][n8][2 + j] * (sa1 * sbv));
                    tB += g; sB += g * lab;
                }
            }
        }
        #pragma unroll
        for (int o = 1; o < 4; o <<= 1) {
            tA += __shfl_xor_sync(0xffffffffu, tA, o);
            sA += __shfl_xor_sync(0xffffffffu, sA, o);
            tB += __shfl_xor_sync(0xffffffffu, tB, o);
            sB += __shfl_xor_sync(0xffffffffu, sB, o);
        }
        if ((lid & 3) == 0) {
            int rowA = rowBase + r0;
            atomicAdd(&g_tot[rowA], tA);
            atomicAdd(&g_s1[rowA], sA);
            atomicAdd(&g_tot[rowA + 8], tB);
            atomicAdd(&g_s1[rowA + 8], sB);
        }
    }
}

// ---------------------------------------------------------------------------
// Kernel 3: probs + argmax + write (parallel over 4096 rows); tier-1 flag.
// ---------------------------------------------------------------------------
__global__ void finalize_kernel(float* __restrict__ out, int out_size) {
    int i = blockIdx.x * blockDim.x + threadIdx.x;
    if (i >= TEST_P) return;
    float tot = g_tot[i], s1 = g_s1[i];
    float p0 = (tot - s1) / tot, p1 = s1 / tot;
    write_row(out, out_size, i, p0, p1);
    if (fabsf(p1 - p0) < TAU1) {
        g_ftot[i] = 0.0f;
        g_fs1[i] = 0.0f;
        int idx = atomicAdd(&g_flagcount, 1);
        g_flaglist[idx] = i;
    }
}

// ---------------------------------------------------------------------------
// Kernel 4: gathered fp16 HMMA GEMM over tier-1 rows (f32->f16 on the fly).
// LAST BLOCK (ticket) rewrites only the F flagged rows + flags tier-2.
// ---------------------------------------------------------------------------
__global__ __launch_bounds__(256)
void fixup16_kernel(const float* __restrict__ train,
                    const float* __restrict__ test,
                    const int* __restrict__ label,
                    float* __restrict__ out, int out_size) {
    __shared__ int sgrow[128];
    __shared__ float sinvA[128];
    __shared__ float sinvB[64];
    __shared__ float slab2[64];
    __shared__ __align__(1024) char tA[16384];   // 128 rows x 128 B (f16)
    __shared__ __align__(1024) char tB[8192];    // 64 rows x 128 B (f16)
    __shared__ int s_last;

    const int F = g_flagcount;
    const int numM = (F + 127) / 128;            // 0 when F == 0
    const int total = numM * 128;                // 128 ntiles of 64 cols
    const int tid = threadIdx.x;
    const int wid = tid >> 5, lid = tid & 31;
    const uint32_t tAb = smem_u32(tA), tBb = smem_u32(tB);

    const int wm = (wid >> 1) * 32;
    const int wn = (wid & 1) * 32;
    const int aRow = wm + (lid & 15);
    const uint32_t aXor = (uint32_t)((aRow & 7) << 4);
    const uint32_t aHi  = (uint32_t)(((lid >> 4) & 1) << 4);
    const uint32_t aRowOff = (uint32_t)(aRow * 128);
    const int bRow = wn + (lid & 7) + (((lid >> 4) & 1) << 3);
    const uint32_t bXor = (uint32_t)((bRow & 7) << 4);
    const uint32_t bHi  = (uint32_t)(((lid >> 3) & 1) << 4);
    const uint32_t bRowOff = (uint32_t)(bRow * 128);

    for (int u = blockIdx.x; u < total; u += gridDim.x) {
        const int mtile = u >> 7;
        const int ntile = u & 127;
        const int colBase = ntile * 64;
        __syncthreads();
        if (tid < 128) {
            int gi = mtile * 128 + tid;
            int row = (gi < F) ? g_flaglist[gi] : 0;
            sgrow[tid] = row;
            sinvA[tid] = g_invte[row];
        } else if (tid < 192) {
            slab2[tid - 128] = (float)label[colBase + tid - 128];
            sinvB[tid - 128] = g_invtr[colBase + tid - 128];
        }
        __syncthreads();

        float acc[2][4][4];
        #pragma unroll
        for (int mi = 0; mi < 2; mi++)
            #pragma unroll
            for (int n = 0; n < 4; n++)
                #pragma unroll
                for (int cc = 0; cc < 4; cc++) acc[mi][n][cc] = 0.0f;

        #pragma unroll 1
        for (int chunk = 0; chunk < 16; chunk++) {
            __syncthreads();
            #pragma unroll
            for (int i = 0; i < 6; i++) {
                int u2 = tid + 256 * i;
                int r, cc;
                const float* src;
                float inv;
                uint32_t dst;
                if (u2 < 1024) {
                    r = u2 >> 3; cc = u2 & 7;
                    src = test + (size_t)sgrow[r] * KDIM + chunk * 64 + cc * 8;
                    inv = sinvA[r];
                    dst = tAb + SW128((uint32_t)(r * 128 + cc * 16));
                } else {
                    int vv = u2 - 1024;
                    r = vv >> 3; cc = vv & 7;
                    src = train + (size_t)(colBase + r) * KDIM + chunk * 64 + cc * 8;
                    inv = sinvB[r];
                    dst = tBb + SW128((uint32_t)(r * 128 + cc * 16));
                }
                float4 v0 = ((const float4*)src)[0];
                float4 v1 = ((const float4*)src)[1];
                union { __half h[8]; uint4 q; } H;
                H.h[0] = __float2half_rn(v0.x * inv);
                H.h[1] = __float2half_rn(v0.y * inv);
                H.h[2] = __float2half_rn(v0.z * inv);
                H.h[3] = __float2half_rn(v0.w * inv);
                H.h[4] = __float2half_rn(v1.x * inv);
                H.h[5] = __float2half_rn(v1.y * inv);
                H.h[6] = __float2half_rn(v1.z * inv);
                H.h[7] = __float2half_rn(v1.w * inv);
                asm volatile("st.shared.v4.b32 [%0], {%1,%2,%3,%4};"
                             :: "r"(dst), "r"(H.q.x), "r"(H.q.y),
                                "r"(H.q.z), "r"(H.q.w) : "memory");
            }
            __syncthreads();
            #pragma unroll
            for (int ks = 0; ks < 4; ks++) {
                uint32_t aoff = ((uint32_t)(ks * 32) + aHi) ^ aXor;
                uint32_t boff = ((uint32_t)(ks * 32) + bHi) ^ bXor;
                uint32_t fa[2][4], fb[2][4];
                #pragma unroll
                for (int mi = 0; mi < 2; mi++)
                    LDSM4(fa[mi][0], fa[mi][1], fa[mi][2], fa[mi][3],
                          tAb + aRowOff + mi * 2048 + aoff);
                #pragma unroll
                for (int nj = 0; nj < 2; nj++)
                    LDSM4(fb[nj][0], fb[nj][1], fb[nj][2], fb[nj][3],
                          tBb + bRowOff + nj * 2048 + boff);
                #pragma unroll
                for (int mi = 0; mi < 2; mi++)
                    #pragma unroll
                    for (int nj = 0; nj < 2; nj++) {
                        HMMA16816(acc[mi][2 * nj],     fa[mi], fb[nj][0], fb[nj][1]);
                        HMMA16816(acc[mi][2 * nj + 1], fa[mi], fb[nj][2], fb[nj][3]);
                    }
            }
        }

        #pragma unroll
        for (int mi = 0; mi < 2; mi++) {
            const int r0 = wm + mi * 16 + (lid >> 2);
            float tAcc = 0.0f, sAcc = 0.0f, tBcc = 0.0f, sBcc = 0.0f;
            #pragma unroll
            for (int n8 = 0; n8 < 4; n8++) {
                #pragma unroll
                for (int j = 0; j < 2; j++) {
                    float lab = slab2[wn + n8 * 8 + 2 * (lid & 3) + j];
                    float g0 = gaussf(acc[mi][n8][j]);
                    tAcc += g0; sAcc += g0 * lab;
                    float g1 = gaussf(acc[mi][n8][2 + j]);
                    tBcc += g1; sBcc += g1 * lab;
                }
            }
            #pragma unroll
            for (int o = 1; o < 4; o <<= 1) {
                tAcc += __shfl_xor_sync(0xffffffffu, tAcc, o);
                sAcc += __shfl_xor_sync(0xffffffffu, sAcc, o);
                tBcc += __shfl_xor_sync(0xffffffffu, tBcc, o);
                sBcc += __shfl_xor_sync(0xffffffffu, sBcc, o);
            }
            if ((lid & 3) == 0) {
                if (mtile * 128 + r0 < F) {
                    int row = sgrow[r0];
                    atomicAdd(&g_ftot[row], tAcc);
                    atomicAdd(&g_fs1[row], sAcc);
                }
                if (mtile * 128 + r0 + 8 < F) {
                    int row = sgrow[r0 + 8];
                    atomicAdd(&g_ftot[row], tBcc);
                    atomicAdd(&g_fs1[row], sBcc);
                }
            }
        }
    }

    // ---- last block: rewrite the F tier-1 rows; flag tier-2 (O(F) serial) ----
    __threadfence();
    __syncthreads();
    if (tid == 0) {
        int tk = atomicAdd(&g_ticketA, 1);
        s_last = (tk == (int)gridDim.x - 1) ? 1 : 0;
    }
    __syncthreads();
    if (s_last) {
        __threadfence();
        for (int k = tid; k < F; k += 256) {
            int i = g_flaglist[k];
            float tot = __ldcg(&g_ftot[i]);
            float s1v = __ldcg(&g_fs1[i]);
            float p0 = (tot - s1v) / tot, p1 = s1v / tot;
            write_row(out, out_size, i, p0, p1);
            if (fabsf(p1 - p0) < TAU2) {
                g_f2tot[i] = 0.0f;
                g_f2s1[i] = 0.0f;
                int idx = atomicAdd(&g_f2count, 1);
                g_f2list[idx] = i;
            }
        }
    }
}

// ---------------------------------------------------------------------------
// Kernel 5: exact fp32 recompute for tier-2 rows; last block rewrites them
// (O(g_f2count) serial, typically 0-3 rows).
// ---------------------------------------------------------------------------
__global__ void fixup32_accum(const float* __restrict__ train,
                              const float* __restrict__ test,
                              const int* __restrict__ label,
                              float* __restrict__ out, int out_size) {
    __shared__ float sa[KDIM];
    __shared__ int s_last;
    const int F2 = g_f2count;
    int total = F2 * NSLICE;
    for (int w = blockIdx.x; w < total; w += gridDim.x) {
        int row   = g_f2list[w / NSLICE];
        int slice = w % NSLICE;
        float ivte = g_invte[row];
        __syncthreads();
        for (int i = threadIdx.x; i < KDIM; i += 256)
            sa[i] = test[(size_t)row * KDIM + i] * ivte;
        __syncthreads();
        int wid = threadIdx.x >> 5, lid = threadIdx.x & 31;
        float tot = 0.0f, s1 = 0.0f;
        for (int r = 0; r < 32; r++) {
            int trow = slice * 256 + wid * 32 + r;
            const float* brow = train + (size_t)trow * KDIM;
            float d = 0.0f;
            #pragma unroll 8
            for (int i = lid; i < KDIM; i += 32) d += sa[i] * brow[i];
            #pragma unroll
            for (int o = 16; o; o >>= 1) d += __shfl_xor_sync(0xffffffffu, d, o);
            if (lid == 0) {
                float dot = d * g_invtr[trow];
                float d2 = fmaxf(2.0f - 2.0f * dot, 0.0f);
                float g = __expf(-2.0f * sqrtf(d2));
                tot += g;
                s1  += g * (float)label[trow];
            }
        }
        if (lid == 0) {
            atomicAdd(&g_f2tot[row], tot);
            atomicAdd(&g_f2s1[row], s1);
        }
    }

    __threadfence();
    __syncthreads();
    if (threadIdx.x == 0) {
        int tk = atomicAdd(&g_ticketB, 1);
        s_last = (tk == (int)gridDim.x - 1) ? 1 : 0;
    }
    __syncthreads();
    if (s_last) {
        __threadfence();
        for (int k = threadIdx.x; k < F2; k += 256) {
            int i = g_f2list[k];
            float tot = __ldcg(&g_f2tot[i]);
            float s1v = __ldcg(&g_f2s1[i]);
            write_row(out, out_size, i, (tot - s1v) / tot, s1v / tot);
        }
    }
}

extern "C" void kernel_launch(void* const* d_in, const int* in_sizes, int n_in,
                              void* d_out, int out_size) {
    const float* train = (const float*)d_in[0];
    const int*   label = (const int*)d_in[1];
    const float* test  = (const float*)d_in[2];

    cudaFuncSetAttribute(pnn_imma, cudaFuncAttributeMaxDynamicSharedMemorySize,
                         SMEM_TOTAL);

    prep_kernel<<<(TRAIN_N + TEST_P) / 8, 256>>>(train, test);

    dim3 grid(TRAIN_N / NT, TEST_P / MT);   // (64, 32)
    pnn_imma<<<grid, THREADS, SMEM_TOTAL>>>(label);

    finalize_kernel<<<(TEST_P + 255) / 256, 256>>>((float*)d_out, out_size);
    fixup16_kernel<<<256, 256>>>(train, test, label, (float*)d_out, out_size);
    fixup32_accum<<<256, 256>>>(train, test, label, (float*)d_out, out_size);
}

// round 16
// speedup vs baseline: 1.2406x; 1.0128x over previous
#include <cuda_runtime.h>
#include <cuda_fp16.h>
#include <cstdint>

// ---------------------------------------------------------------------------
// PNN_43095701848191 — build r16: R15 + persistent-CTA IMMA GEMM.
// 296 persistent CTAs (2/SM), each streams ~7 tiles' K-chunks through ONE
// continuous 3-stage cp.async pipeline, so each tile's fill hides under the
// previous tile's tail MMAs + epilogue (the per-wave fill exposure was the
// bulk of the 90us-vs-73us-floor gap).
//
//  prep:     warp-per-row norms + int8 quantization (MLP=8, shuffle-only).
//  imma:     persistent; per tile: 8 K-chunks of 128 s8 (SW128),
//            mma.sync.m16n8k32.s8, warp tile 32x64; epilogue Gauss + class
//            sums (atomics); metadata staged at tile start, acc re-zeroed.
//  finalize: probs + argmax + write (parallel); tier-1 flag (|gap| < 4e-4).
//  fixup16:  gathered fp16 HMMA GEMM over tier-1 rows; last block rewrites
//            the F tier-1 rows + flags tier-2 (|gap| < 1e-5).
//  fixup32:  exact fp32 recompute of tier-2 rows; last block rewrites them.
// ---------------------------------------------------------------------------

#define TRAIN_N 8192
#define TEST_P  4096
#define KDIM    1024

#define MT 128
#define NT 128
#define STAGES 3
#define THREADS 256
#define NCTAS 296                     // 2 per SM x 148 SMs
#define TOTAL_TILES ((TRAIN_N / NT) * (TEST_P / MT))   // 2048

#define TAU1 4e-4f
#define TAU2 1e-5f
#define NSLICE 32

__device__ __align__(16) uint32_t g_Aq[TEST_P * KDIM / 4];
__device__ __align__(16) uint32_t g_Bq[TRAIN_N * KDIM / 4];
__device__ float g_sa[TEST_P];
__device__ float g_sb[TRAIN_N];
__device__ float g_invte[TEST_P];
__device__ float g_invtr[TRAIN_N];
__device__ float g_tot[TEST_P];
__device__ float g_s1[TEST_P];
__device__ int   g_flaglist[TEST_P];
__device__ int   g_flagcount;
__device__ float g_ftot[TEST_P];
__device__ float g_fs1[TEST_P];
__device__ int   g_f2list[TEST_P];
__device__ int   g_f2count;
__device__ float g_f2tot[TEST_P];
__device__ float g_f2s1[TEST_P];
__device__ int   g_ticketA, g_ticketB;

__device__ __forceinline__ uint32_t smem_u32(const void* p) {
    uint32_t a;
    asm("{ .reg .u64 t; cvta.to.shared.u64 t, %1; cvt.u32.u64 %0, t; }"
        : "=r"(a) : "l"(p));
    return a;
}

#define SW128(o) ((o) ^ (((o) >> 3) & 0x70))

#define LDSM4(r0, r1, r2, r3, a) \
    asm volatile("ldmatrix.sync.aligned.m8n8.x4.shared.b16 {%0,%1,%2,%3}, [%4];" \
                 : "=r"(r0), "=r"(r1), "=r"(r2), "=r"(r3) : "r"(a))

#define IMMA16832(d, a, b0, b1) \
    asm volatile("mma.sync.aligned.m16n8k32.row.col.s32.s8.s8.s32 " \
                 "{%0,%1,%2,%3}, {%4,%5,%6,%7}, {%8,%9}, {%0,%1,%2,%3};" \
                 : "+r"((d)[0]), "+r"((d)[1]), "+r"((d)[2]), "+r"((d)[3]) \
                 : "r"((a)[0]), "r"((a)[1]), "r"((a)[2]), "r"((a)[3]), \
                   "r"(b0), "r"(b1))

#define HMMA16816(d, a, b0, b1) \
    asm volatile("mma.sync.aligned.m16n8k16.row.col.f32.f16.f16.f32 " \
                 "{%0,%1,%2,%3}, {%4,%5,%6,%7}, {%8,%9}, {%0,%1,%2,%3};" \
                 : "+f"((d)[0]), "+f"((d)[1]), "+f"((d)[2]), "+f"((d)[3]) \
                 : "r"((a)[0]), "r"((a)[1]), "r"((a)[2]), "r"((a)[3]), \
                   "r"(b0), "r"(b1))

#define EX2(out, in) asm("ex2.approx.f32 %0, %1;" : "=f"(out) : "f"(in))
#define GAUSS_C (-2.885390082f)   /* -2 * log2(e) */

__device__ __forceinline__ float gaussf(float dot) {
    float d2 = fmaxf(2.0f - 2.0f * dot, 0.0f);
    float d;
    asm("sqrt.approx.f32 %0, %1;" : "=f"(d) : "f"(d2));
    float g; EX2(g, GAUSS_C * d);
    return g;
}

__device__ __forceinline__ void write_row(float* out, int out_size, int i,
                                          float p0, float p1) {
    float res = (p1 > p0) ? 1.0f : 0.0f;
    if (out_size >= TEST_P * 3) {
        out[i] = res;
        out[TEST_P + 2 * i]     = p0;
        out[TEST_P + 2 * i + 1] = p1;
    } else if (out_size == TEST_P * 2) {
        out[2 * i] = p0;
        out[2 * i + 1] = p1;
    } else {
        out[i] = res;
    }
}

// ---------------------------------------------------------------------------
// Kernel 1: warp-per-row norms + int8 quantization (MLP=8, no smem).
// ---------------------------------------------------------------------------
__global__ void prep_kernel(const float* __restrict__ train,
                            const float* __restrict__ test) {
    const int warp = blockIdx.x * 8 + (threadIdx.x >> 5);  // row 0..12287
    const int lane = threadIdx.x & 31;
    const bool isTrain = warp < TRAIN_N;
    const float* row = isTrain ? train + (size_t)warp * KDIM
                               : test + (size_t)(warp - TRAIN_N) * KDIM;

    float4 v[8];
    #pragma unroll
    for (int k = 0; k < 8; k++) v[k] = ((const float4*)row)[lane + 32 * k];

    float s = 0.0f, m = 0.0f;
    #pragma unroll
    for (int k = 0; k < 8; k++) {
        s += v[k].x * v[k].x + v[k].y * v[k].y + v[k].z * v[k].z + v[k].w * v[k].w;
        m = fmaxf(m, fmaxf(fmaxf(fabsf(v[k].x), fabsf(v[k].y)),
                           fmaxf(fabsf(v[k].z), fabsf(v[k].w))));
    }
    #pragma unroll
    for (int o = 16; o; o >>= 1) {
        s += __shfl_xor_sync(0xffffffffu, s, o);
        m = fmaxf(m, __shfl_xor_sync(0xffffffffu, m, o));
    }
    const float inv = rsqrtf(s);
    const float maxn = m * inv;
    const float qs = 127.0f / maxn;

    uint32_t* dstq = isTrain ? g_Bq + (size_t)warp * 256
                             : g_Aq + (size_t)(warp - TRAIN_N) * 256;
    #pragma unroll
    for (int k = 0; k < 8; k++) {
        int q0 = __float2int_rn(v[k].x * inv * qs);
        int q1 = __float2int_rn(v[k].y * inv * qs);
        int q2 = __float2int_rn(v[k].z * inv * qs);
        int q3 = __float2int_rn(v[k].w * inv * qs);
        dstq[lane + 32 * k] =
            (uint32_t)(q0 & 255) | ((uint32_t)(q1 & 255) << 8) |
            ((uint32_t)(q2 & 255) << 16) | ((uint32_t)(q3 & 255) << 24);
    }

    if (lane == 0) {
        if (isTrain) {
            g_invtr[warp] = inv;
            g_sb[warp] = maxn * (1.0f / 127.0f);
        } else {
            int bi = warp - TRAIN_N;
            g_invte[bi] = inv;
            g_sa[bi] = maxn * (1.0f / 127.0f);
            g_tot[bi] = 0.0f;
            g_s1[bi] = 0.0f;
        }
        if (warp == 0) {
            g_flagcount = 0; g_f2count = 0;
            g_ticketA = 0; g_ticketB = 0;
        }
    }
}

// ---------------------------------------------------------------------------
// Kernel 2: persistent int8 IMMA GEMM, continuous cross-tile chunk stream.
// smem: [0,512) labels; [512,1024) col scales; [1024,1536) row scales;
//       tiles at 2048, 3 x 32 KB.
// ---------------------------------------------------------------------------
#define SLAB_OFF  0
#define SSB_OFF   512
#define SSA_OFF   1024
#define TILES_OFF 2048
#define STAGE_BYTES (MT * 128 + NT * 128)   // 32768
#define B_OFF       (MT * 128)              // 16384
#define SMEM_TOTAL  (TILES_OFF + STAGES * STAGE_BYTES)  // 100352

// tile index -> (rowBase, colBase); chunk g -> tile g>>3, k-chunk g&7
__device__ __forceinline__ void load_chunk_g(int tid, uint32_t sb, int bid,
                                             int g) {
    const int tile = bid + (g >> 3) * NCTAS;
    const int c = g & 7;
    const int stage = g % STAGES;
    const int colBase = (tile & 63) * NT;
    const int rowBase = (tile >> 6) * MT;
    uint32_t base = sb + TILES_OFF + (uint32_t)stage * STAGE_BYTES;
    const char* srcA = (const char*)g_Aq + (size_t)rowBase * KDIM + (size_t)c * 128;
    const char* srcB = (const char*)g_Bq + (size_t)colBase * KDIM + (size_t)c * 128;
    #pragma unroll
    for (int i = 0; i < 8; i++) {
        int u = tid + THREADS * i;
        const char* src;
        uint32_t dst;
        if (u < 1024) {                 // A tile: 128 rows x 128 B
            int r = u >> 3, cc = u & 7;
            src = srcA + (size_t)r * KDIM + cc * 16;
            dst = base + SW128((uint32_t)(r * 128 + cc * 16));
        } else {                        // B tile: 128 rows x 128 B
            int vv = u - 1024;
            int r = vv >> 3, cc = vv & 7;
            src = srcB + (size_t)r * KDIM + cc * 16;
            dst = base + B_OFF + SW128((uint32_t)(r * 128 + cc * 16));
        }
        asm volatile("cp.async.cg.shared.global [%0], [%1], 16;"
                     :: "r"(dst), "l"(src));
    }
    asm volatile("cp.async.commit_group;" ::: "memory");
}

__global__ __launch_bounds__(THREADS, 2)
void pnn_imma(const int* __restrict__ label) {
    extern __shared__ __align__(1024) char smem[];
    uint32_t sb = smem_u32(smem);
    const int tid = threadIdx.x;
    const int wid = tid >> 5, lid = tid & 31;
    const int bid = blockIdx.x;

    float* slab = (float*)(smem + SLAB_OFF);
    float* ssb  = (float*)(smem + SSB_OFF);
    float* ssa  = (float*)(smem + SSA_OFF);

    // warp layout: 4 (m) x 2 (n); warp tile 32 x 64
    const int wm = (wid >> 1) * 32;
    const int wn = (wid & 1) * 64;

    const int aRow = wm + (lid & 15);
    const uint32_t aXor = (uint32_t)((aRow & 7) << 4);
    const uint32_t aHi  = (uint32_t)(((lid >> 4) & 1) << 4);
    const uint32_t aRowOff = (uint32_t)(aRow * 128);
    const int bRow = wn + (lid & 7) + (((lid >> 4) & 1) << 3);
    const uint32_t bXor = (uint32_t)((bRow & 7) << 4);
    const uint32_t bHi  = (uint32_t)(((lid >> 3) & 1) << 4);
    const uint32_t bRowOff = (uint32_t)(bRow * 128);

    const int nT = (TOTAL_TILES - 1 - bid) / NCTAS + 1;
    const int NG = nT * 8;

    int acc[2][8][4];
    #pragma unroll
    for (int mi = 0; mi < 2; mi++)
        #pragma unroll
        for (int n = 0; n < 8; n++)
            #pragma unroll
            for (int c = 0; c < 4; c++) acc[mi][n][c] = 0;

    load_chunk_g(tid, sb, bid, 0);
    load_chunk_g(tid, sb, bid, 1);

    #pragma unroll 1
    for (int g = 0; g < NG; g++) {
        if (g + 1 < NG) {
            asm volatile("cp.async.wait_group 1;" ::: "memory");
        } else {
            asm volatile("cp.async.wait_group 0;" ::: "memory");
        }
        __syncthreads();
        if (g + 2 < NG) load_chunk_g(tid, sb, bid, g + 2);

        const int tile = bid + (g >> 3) * NCTAS;
        if ((g & 7) == 0) {            // stage this tile's metadata
            const int colBase = (tile & 63) * NT;
            const int rowBase = (tile >> 6) * MT;
            if (tid < NT)          slab[tid] = (float)label[colBase + tid];
            else if (tid < 2 * NT) ssb[tid - NT] = g_sb[colBase + tid - NT];
            if (tid < MT)          ssa[tid] = g_sa[rowBase + tid];
        }

        const uint32_t base = sb + TILES_OFF + (uint32_t)(g % STAGES) * STAGE_BYTES;
        #pragma unroll
        for (int ks = 0; ks < 4; ks++) {
            uint32_t aoff = ((uint32_t)(ks * 32) + aHi) ^ aXor;
            uint32_t boff = ((uint32_t)(ks * 32) + bHi) ^ bXor;
            uint32_t fa[2][4], fb[4][4];
            #pragma unroll
            for (int mi = 0; mi < 2; mi++)
                LDSM4(fa[mi][0], fa[mi][1], fa[mi][2], fa[mi][3],
                      base + aRowOff + mi * 2048 + aoff);
            #pragma unroll
            for (int nj = 0; nj < 4; nj++)
                LDSM4(fb[nj][0], fb[nj][1], fb[nj][2], fb[nj][3],
                      base + B_OFF + bRowOff + nj * 2048 + boff);
            #pragma unroll
            for (int mi = 0; mi < 2; mi++)
                #pragma unroll
                for (int nj = 0; nj < 4; nj++) {
                    IMMA16832(acc[mi][2 * nj],     fa[mi], fb[nj][0], fb[nj][1]);
                    IMMA16832(acc[mi][2 * nj + 1], fa[mi], fb[nj][2], fb[nj][3]);
                }
        }

        if ((g & 7) == 7) {
            // ---- epilogue for this tile (next tile's loads are in flight) ----
            const int rowBase = (tile >> 6) * MT;
            #pragma unroll
            for (int mi = 0; mi < 2; mi++) {
                const int r0 = wm + mi * 16 + (lid >> 2);
                const float sa0 = ssa[r0];
                const float sa1 = ssa[r0 + 8];
                float tA = 0.0f, sA = 0.0f, tB = 0.0f, sB = 0.0f;
                #pragma unroll
                for (int n8 = 0; n8 < 8; n8++) {
                    #pragma unroll
                    for (int j = 0; j < 2; j++) {
                        const int col = wn + n8 * 8 + 2 * (lid & 3) + j;
                        const float lab = slab[col];
                        const float sbv = ssb[col];
                        {
                            float gg = gaussf((float)acc[mi][n8][j] * (sa0 * sbv));
                            tA += gg; sA += gg * lab;
                        }
                        {
                            float gg = gaussf((float)acc[mi][n8][2 + j] * (sa1 * sbv));
                            tB += gg; sB += gg * lab;
                        }
                    }
                }
                #pragma unroll
                for (int o = 1; o < 4; o <<= 1) {
                    tA += __shfl_xor_sync(0xffffffffu, tA, o);
                    sA += __shfl_xor_sync(0xffffffffu, sA, o);
                    tB += __shfl_xor_sync(0xffffffffu, tB, o);
                    sB += __shfl_xor_sync(0xffffffffu, sB, o);
                }
                if ((lid & 3) == 0) {
                    int rowA = rowBase + r0;
                    atomicAdd(&g_tot[rowA], tA);
                    atomicAdd(&g_s1[rowA], sA);
                    atomicAdd(&g_tot[rowA + 8], tB);
                    atomicAdd(&g_s1[rowA + 8], sB);
                }
            }
            #pragma unroll
            for (int mi = 0; mi < 2; mi++)
                #pragma unroll
                for (int n = 0; n < 8; n++)
                    #pragma unroll
                    for (int c = 0; c < 4; c++) acc[mi][n][c] = 0;
        }
    }
}

// ---------------------------------------------------------------------------
// Kernel 3: probs + argmax + write (parallel over 4096 rows); tier-1 flag.
// ---------------------------------------------------------------------------
__global__ void finalize_kernel(float* __restrict__ out, int out_size) {
    int i = blockIdx.x * blockDim.x + threadIdx.x;
    if (i >= TEST_P) return;
    float tot = g_tot[i], s1 = g_s1[i];
    float p0 = (tot - s1) / tot, p1 = s1 / tot;
    write_row(out, out_size, i, p0, p1);
    if (fabsf(p1 - p0) < TAU1) {
        g_ftot[i] = 0.0f;
        g_fs1[i] = 0.0f;
        int idx = atomicAdd(&g_flagcount, 1);
        g_flaglist[idx] = i;
    }
}

// ---------------------------------------------------------------------------
// Kernel 4: gathered fp16 HMMA GEMM over tier-1 rows (f32->f16 on the fly).
// LAST BLOCK (ticket) rewrites only the F flagged rows + flags tier-2.
// ---------------------------------------------------------------------------
__global__ __launch_bounds__(256)
void fixup16_kernel(const float* __restrict__ train,
                    const float* __restrict__ test,
                    const int* __restrict__ label,
                    float* __restrict__ out, int out_size) {
    __shared__ int sgrow[128];
    __shared__ float sinvA[128];
    __shared__ float sinvB[64];
    __shared__ float slab2[64];
    __shared__ __align__(1024) char tA[16384];   // 128 rows x 128 B (f16)
    __shared__ __align__(1024) char tB[8192];    // 64 rows x 128 B (f16)
    __shared__ int s_last;

    const int F = g_flagcount;
    const int numM = (F + 127) / 128;            // 0 when F == 0
    const int total = numM * 128;                // 128 ntiles of 64 cols
    const int tid = threadIdx.x;
    const int wid = tid >> 5, lid = tid & 31;
    const uint32_t tAb = smem_u32(tA), tBb = smem_u32(tB);

    const int wm = (wid >> 1) * 32;
    const int wn = (wid & 1) * 32;
    const int aRow = wm + (lid & 15);
    const uint32_t aXor = (uint32_t)((aRow & 7) << 4);
    const uint32_t aHi  = (uint32_t)(((lid >> 4) & 1) << 4);
    const uint32_t aRowOff = (uint32_t)(aRow * 128);
    const int bRow = wn + (lid & 7) + (((lid >> 4) & 1) << 3);
    const uint32_t bXor = (uint32_t)((bRow & 7) << 4);
    const uint32_t bHi  = (uint32_t)(((lid >> 3) & 1) << 4);
    const uint32_t bRowOff = (uint32_t)(bRow * 128);

    for (int u = blockIdx.x; u < total; u += gridDim.x) {
        const int mtile = u >> 7;
        const int ntile = u & 127;
        const int colBase = ntile * 64;
        __syncthreads();
        if (tid < 128) {
            int gi = mtile * 128 + tid;
            int row = (gi < F) ? g_flaglist[gi] : 0;
            sgrow[tid] = row;
            sinvA[tid] = g_invte[row];
        } else if (tid < 192) {
            slab2[tid - 128] = (float)label[colBase + tid - 128];
            sinvB[tid - 128] = g_invtr[colBase + tid - 128];
        }
        __syncthreads();

        float acc[2][4][4];
        #pragma unroll
        for (int mi = 0; mi < 2; mi++)
            #pragma unroll
            for (int n = 0; n < 4; n++)
                #pragma unroll
                for (int cc = 0; cc < 4; cc++) acc[mi][n][cc] = 0.0f;

        #pragma unroll 1
        for (int chunk = 0; chunk < 16; chunk++) {
            __syncthreads();
            #pragma unroll
            for (int i = 0; i < 6; i++) {
                int u2 = tid + 256 * i;
                int r, cc;
                const float* src;
                float inv;
                uint32_t dst;
                if (u2 < 1024) {
                    r = u2 >> 3; cc = u2 & 7;
                    src = test + (size_t)sgrow[r] * KDIM + chunk * 64 + cc * 8;
                    inv = sinvA[r];
                    dst = tAb + SW128((uint32_t)(r * 128 + cc * 16));
                } else {
                    int vv = u2 - 1024;
                    r = vv >> 3; cc = vv & 7;
                    src = train + (size_t)(colBase + r) * KDIM + chunk * 64 + cc * 8;
                    inv = sinvB[r];
                    dst = tBb + SW128((uint32_t)(r * 128 + cc * 16));
                }
                float4 v0 = ((const float4*)src)[0];
                float4 v1 = ((const float4*)src)[1];
                union { __half h[8]; uint4 q; } H;
                H.h[0] = __float2half_rn(v0.x * inv);
                H.h[1] = __float2half_rn(v0.y * inv);
                H.h[2] = __float2half_rn(v0.z * inv);
                H.h[3] = __float2half_rn(v0.w * inv);
                H.h[4] = __float2half_rn(v1.x * inv);
                H.h[5] = __float2half_rn(v1.y * inv);
                H.h[6] = __float2half_rn(v1.z * inv);
                H.h[7] = __float2half_rn(v1.w * inv);
                asm volatile("st.shared.v4.b32 [%0], {%1,%2,%3,%4};"
                             :: "r"(dst), "r"(H.q.x), "r"(H.q.y),
                                "r"(H.q.z), "r"(H.q.w) : "memory");
            }
            __syncthreads();
            #pragma unroll
            for (int ks = 0; ks < 4; ks++) {
                uint32_t aoff = ((uint32_t)(ks * 32) + aHi) ^ aXor;
                uint32_t boff = ((uint32_t)(ks * 32) + bHi) ^ bXor;
                uint32_t fa[2][4], fb[2][4];
                #pragma unroll
                for (int mi = 0; mi < 2; mi++)
                    LDSM4(fa[mi][0], fa[mi][1], fa[mi][2], fa[mi][3],
                          tAb + aRowOff + mi * 2048 + aoff);
                #pragma unroll
                for (int nj = 0; nj < 2; nj++)
                    LDSM4(fb[nj][0], fb[nj][1], fb[nj][2], fb[nj][3],
                          tBb + bRowOff + nj * 2048 + boff);
                #pragma unroll
                for (int mi = 0; mi < 2; mi++)
                    #pragma unroll
                    for (int nj = 0; nj < 2; nj++) {
                        HMMA16816(acc[mi][2 * nj],     fa[mi], fb[nj][0], fb[nj][1]);
                        HMMA16816(acc[mi][2 * nj + 1], fa[mi], fb[nj][2], fb[nj][3]);
                    }
            }
        }

        #pragma unroll
        for (int mi = 0; mi < 2; mi++) {
            const int r0 = wm + mi * 16 + (lid >> 2);
            float tAcc = 0.0f, sAcc = 0.0f, tBcc = 0.0f, sBcc = 0.0f;
            #pragma unroll
            for (int n8 = 0; n8 < 4; n8++) {
                #pragma unroll
                for (int j = 0; j < 2; j++) {
                    float lab = slab2[wn + n8 * 8 + 2 * (lid & 3) + j];
                    float g0 = gaussf(acc[mi][n8][j]);
                    tAcc += g0; sAcc += g0 * lab;
                    float g1 = gaussf(acc[mi][n8][2 + j]);
                    tBcc += g1; sBcc += g1 * lab;
                }
            }
            #pragma unroll
            for (int o = 1; o < 4; o <<= 1) {
                tAcc += __shfl_xor_sync(0xffffffffu, tAcc, o);
                sAcc += __shfl_xor_sync(0xffffffffu, sAcc, o);
                tBcc += __shfl_xor_sync(0xffffffffu, tBcc, o);
                sBcc += __shfl_xor_sync(0xffffffffu, sBcc, o);
            }
            if ((lid & 3) == 0) {
                if (mtile * 128 + r0 < F) {
                    int row = sgrow[r0];
                    atomicAdd(&g_ftot[row], tAcc);
                    atomicAdd(&g_fs1[row], sAcc);
                }
                if (mtile * 128 + r0 + 8 < F) {
                    int row = sgrow[r0 + 8];
                    atomicAdd(&g_ftot[row], tBcc);
                    atomicAdd(&g_fs1[row], sBcc);
                }
            }
        }
    }

    // ---- last block: rewrite the F tier-1 rows; flag tier-2 (O(F) serial) ----
    __threadfence();
    __syncthreads();
    if (tid == 0) {
        int tk = atomicAdd(&g_ticketA, 1);
        s_last = (tk == (int)gridDim.x - 1) ? 1 : 0;
    }
    __syncthreads();
    if (s_last) {
        __threadfence();
        for (int k = tid; k < F; k += 256) {
            int i = g_flaglist[k];
            float tot = __ldcg(&g_ftot[i]);
            float s1v = __ldcg(&g_fs1[i]);
            float p0 = (tot - s1v) / tot, p1 = s1v / tot;
            write_row(out, out_size, i, p0, p1);
            if (fabsf(p1 - p0) < TAU2) {
                g_f2tot[i] = 0.0f;
                g_f2s1[i] = 0.0f;
                int idx = atomicAdd(&g_f2count, 1);
                g_f2list[idx] = i;
            }
        }
    }
}

// ---------------------------------------------------------------------------
// Kernel 5: exact fp32 recompute for tier-2 rows; last block rewrites them.
// ---------------------------------------------------------------------------
__global__ void fixup32_accum(const float* __restrict__ train,
                              const float* __restrict__ test,
                              const int* __restrict__ label,
                              float* __restrict__ out, int out_size) {
    __shared__ float sa[KDIM];
    __shared__ int s_last;
    const int F2 = g_f2count;
    int total = F2 * NSLICE;
    for (int w = blockIdx.x; w < total; w += gridDim.x) {
        int row   = g_f2list[w / NSLICE];
        int slice = w % NSLICE;
        float ivte = g_invte[row];
        __syncthreads();
        for (int i = threadIdx.x; i < KDIM; i += 256)
            sa[i] = test[(size_t)row * KDIM + i] * ivte;
        __syncthreads();
        int wid = threadIdx.x >> 5, lid = threadIdx.x & 31;
        float tot = 0.0f, s1 = 0.0f;
        for (int r = 0; r < 32; r++) {
            int trow = slice * 256 + wid * 32 + r;
            const float* brow = train + (size_t)trow * KDIM;
            float d = 0.0f;
            #pragma unroll 8
            for (int i = lid; i < KDIM; i += 32) d += sa[i] * brow[i];
            #pragma unroll
            for (int o = 16; o; o >>= 1) d += __shfl_xor_sync(0xffffffffu, d, o);
            if (lid == 0) {
                float dot = d * g_invtr[trow];
                float d2 = fmaxf(2.0f - 2.0f * dot, 0.0f);
                float g = __expf(-2.0f * sqrtf(d2));
                tot += g;
                s1  += g * (float)label[trow];
            }
        }
        if (lid == 0) {
            atomicAdd(&g_f2tot[row], tot);
            atomicAdd(&g_f2s1[row], s1);
        }
    }

    __threadfence();
    __syncthreads();
    if (threadIdx.x == 0) {
        int tk = atomicAdd(&g_ticketB, 1);
        s_last = (tk == (int)gridDim.x - 1) ? 1 : 0;
    }
    __syncthreads();
    if (s_last) {
        __threadfence();
        for (int k = threadIdx.x; k < F2; k += 256) {
            int i = g_f2list[k];
            float tot = __ldcg(&g_f2tot[i]);
            float s1v = __ldcg(&g_f2s1[i]);
            write_row(out, out_size, i, (tot - s1v) / tot, s1v / tot);
        }
    }
}

extern "C" void kernel_launch(void* const* d_in, const int* in_sizes, int n_in,
                              void* d_out, int out_size) {
    const float* train = (const float*)d_in[0];
    const int*   label = (const int*)d_in[1];
    const float* test  = (const float*)d_in[2];

    cudaFuncSetAttribute(pnn_imma, cudaFuncAttributeMaxDynamicSharedMemorySize,
                         SMEM_TOTAL);

    prep_kernel<<<(TRAIN_N + TEST_P) / 8, 256>>>(train, test);

    pnn_imma<<<NCTAS, THREADS, SMEM_TOTAL>>>(label);

    finalize_kernel<<<(TEST_P + 255) / 256, 256>>>((float*)d_out, out_size);
    fixup16_kernel<<<256, 256>>>(train, test, label, (float*)d_out, out_size);
    fixup32_accum<<<256, 256>>>(train, test, label, (float*)d_out, out_size);
}